// round 12
// baseline (speedup 1.0000x reference)
#include <cuda_runtime.h>
#include <cuda_bf16.h>
#include <cstdint>

#define N_NODES 50000
#define N_EDGES 600000
#define NB      64
#define D       128      // F == H == U
#define NLAYERS 4

#define EPAD 132   // padded row stride for 128-wide smem tiles (node/global)
#define HPAD 36    // padded row stride for 32-wide K chunks (node)

#define LDA 136                      // bf16 row stride for mma tiles (272B, 16B-aligned)
#define WTILE_BYTES (128 * LDA * 2)  // 34816 bytes per 128x128 bf16 tile
#define NTILES ((N_EDGES + 127) / 128)   // 4688 edge tiles

// ===========================================================================
// Scratch (no allocations allowed -> __device__ globals)
// ===========================================================================
__device__ float g_x[2][N_NODES * D];
__device__ float g_u[2][NB * D];
__device__ float g_agg[N_NODES * D];
__device__ float g_cnt[N_NODES];
__device__ float g_xsum[NB * D];
__device__ float g_bcnt[NB];
// transposed/split bf16 weight tiles [n][k], padded LDA: [layer][w1,w2][hi,lo]
__device__ __align__(16) unsigned char g_wt[16 * WTILE_BYTES];

__device__ __forceinline__ void red_add_v4(float* addr, float a, float b, float c, float d) {
    asm volatile("red.global.add.v4.f32 [%0], {%1,%2,%3,%4};"
                 :: "l"(addr), "f"(a), "f"(b), "f"(c), "f"(d) : "memory");
}
__device__ __forceinline__ void red_add_v2(float* addr, float a, float b) {
    asm volatile("red.global.add.v2.f32 [%0], {%1,%2};"
                 :: "l"(addr), "f"(a), "f"(b) : "memory");
}

__device__ __forceinline__ uint32_t smem_u32(const void* p) {
    uint32_t a;
    asm("{ .reg .u64 t; cvta.to.shared.u64 t, %1; cvt.u32.u64 %0, t; }" : "=r"(a) : "l"(p));
    return a;
}

__device__ __forceinline__ void ldsm4(uint32_t addr, uint32_t r[4]) {
    asm volatile("ldmatrix.sync.aligned.m8n8.x4.shared.b16 {%0,%1,%2,%3}, [%4];"
                 : "=r"(r[0]), "=r"(r[1]), "=r"(r[2]), "=r"(r[3]) : "r"(addr));
}

__device__ __forceinline__ void mma16816(float d[4], const uint32_t a[4],
                                         uint32_t b0, uint32_t b1) {
    asm volatile(
        "mma.sync.aligned.m16n8k16.row.col.f32.bf16.bf16.f32 "
        "{%0,%1,%2,%3}, {%4,%5,%6,%7}, {%8,%9}, {%0,%1,%2,%3};"
        : "+f"(d[0]), "+f"(d[1]), "+f"(d[2]), "+f"(d[3])
        : "r"(a[0]), "r"(a[1]), "r"(a[2]), "r"(a[3]), "r"(b0), "r"(b1));
}

__device__ __forceinline__ uint32_t pack_bf16_hi(float f0, float f1) {
    return ((uint32_t)__bfloat16_as_ushort(__float2bfloat16_rn(f1)) << 16)
         |  (uint32_t)__bfloat16_as_ushort(__float2bfloat16_rn(f0));
}

// ===========================================================================
// One-time kernels
// ===========================================================================
__global__ void count_edges_kernel(const int* __restrict__ ei, float* __restrict__ cnt) {
    int e = blockIdx.x * 256 + threadIdx.x;
    if (e < N_EDGES) atomicAdd(&cnt[ei[N_EDGES + e]], 1.0f);
}
__global__ void count_batch_kernel(const int* __restrict__ batch, float* __restrict__ bcnt) {
    int n = blockIdx.x * 256 + threadIdx.x;
    if (n < N_NODES) atomicAdd(&bcnt[batch[n]], 1.0f);
}

// Transpose+split W (row-major [K=128, N=128]) into bf16 hi/lo tiles [n][k], LDA pad.
__global__ void prep_weights_kernel(const float* __restrict__ n1w1,
                                    const float* __restrict__ n1w2) {
    int b = blockIdx.x;                 // 0..7: (layer, w1/w2)
    int l = b >> 1, which = b & 1;
    const float* w = (which ? n1w2 : n1w1) + (size_t)l * D * D;
    unsigned char* thi = g_wt + ((size_t)b * 2 + 0) * WTILE_BYTES;
    unsigned char* tlo = g_wt + ((size_t)b * 2 + 1) * WTILE_BYTES;
    for (int idx = threadIdx.x; idx < 128 * 32; idx += 256) {
        int n = idx >> 5, kq = (idx & 31) << 2;
        unsigned short hh[4], ll[4];
#pragma unroll
        for (int q = 0; q < 4; ++q) {
            float f = w[(kq + q) * D + n];
            __nv_bfloat16 h = __float2bfloat16_rn(f);
            float r = f - __bfloat162float(h);
            hh[q] = __bfloat16_as_ushort(h);
            ll[q] = __bfloat16_as_ushort(__float2bfloat16_rn(r));
        }
        uint32_t o = (uint32_t)(n * LDA + kq) * 2;
        *(uint2*)(thi + o) = make_uint2(((uint32_t)hh[1] << 16) | hh[0],
                                        ((uint32_t)hh[3] << 16) | hh[2]);
        *(uint2*)(tlo + o) = make_uint2(((uint32_t)ll[1] << 16) | ll[0],
                                        ((uint32_t)ll[3] << 16) | ll[2]);
    }
}

// ===========================================================================
// Edge MLP via mma.sync (split-bf16, 3-term), persistent CTAs,
// all four weight tiles resident in smem, grid-stride over edge tiles.
// ===========================================================================
#define SM_COLS   0                               // int[128]
#define SM_B1     512                             // float[128]
#define SM_B2     1024                            // float[128]
#define A_HI_OFF  2048
#define A_LO_OFF  (A_HI_OFF  + WTILE_BYTES)
#define W1_HI_OFF (A_LO_OFF  + WTILE_BYTES)
#define W1_LO_OFF (W1_HI_OFF + WTILE_BYTES)
#define W2_HI_OFF (W1_LO_OFF + WTILE_BYTES)
#define W2_LO_OFF (W2_HI_OFF + WTILE_BYTES)
static const int EDGE_SMEM = W2_LO_OFF + WTILE_BYTES;   // 210944
#define ETHREADS 512

// One split GEMM pass over K=128: D += Ahi@Whi + Ahi@Wlo + Alo@Whi.
// Warp tile 32x32: d[2 m16][4 n8][4].
// Pass-structured so same-accumulator MMAs are 8 instructions apart
// (the naive per-(p,h,mt) 3-term ordering creates 3 back-to-back dependent
// HMMAs into the same d regs -> issue rate collapses to ~17%).
// Alo fragments are loaded LATE (just before pass 3) to keep peak registers
// flat and avoid spilling at the 128-reg cap.
__device__ __forceinline__ void gemm_split32(uint32_t aHi, uint32_t aLo,
                                             uint32_t wHi, uint32_t wLo,
                                             int mrow, int ncol, int lane,
                                             float d[2][4][4]) {
    const int a_row  = lane & 15;
    const int a_koff = (lane >> 4) << 3;
    const int b_nrow = ((lane >> 4) << 3) + (lane & 7);
    const int b_koff = ((lane >> 3) & 1) << 3;
#pragma unroll
    for (int ks = 0; ks < 8; ++ks) {
        const int kb = ks * 16;
        uint32_t ah[2][4], al[2][4], bh[2][4], bl[2][4];
#pragma unroll
        for (int mt = 0; mt < 2; ++mt) {
            uint32_t off = (uint32_t)(((mrow + mt * 16 + a_row) * LDA + kb + a_koff) * 2);
            ldsm4(aHi + off, ah[mt]);
        }
#pragma unroll
        for (int p = 0; p < 2; ++p) {
            uint32_t off = (uint32_t)(((ncol + p * 16 + b_nrow) * LDA + kb + b_koff) * 2);
            ldsm4(wHi + off, bh[p]);
            ldsm4(wLo + off, bl[p]);
        }
        // pass 1: Ahi @ Whi -- 8 MMAs, all distinct accumulators
#pragma unroll
        for (int p = 0; p < 2; ++p)
#pragma unroll
            for (int h = 0; h < 2; ++h)
#pragma unroll
                for (int mt = 0; mt < 2; ++mt)
                    mma16816(d[mt][p * 2 + h], ah[mt], bh[p][2 * h], bh[p][2 * h + 1]);
        // pass 2: Ahi @ Wlo
#pragma unroll
        for (int p = 0; p < 2; ++p)
#pragma unroll
            for (int h = 0; h < 2; ++h)
#pragma unroll
                for (int mt = 0; mt < 2; ++mt)
                    mma16816(d[mt][p * 2 + h], ah[mt], bl[p][2 * h], bl[p][2 * h + 1]);
        // late Alo load, then pass 3: Alo @ Whi
#pragma unroll
        for (int mt = 0; mt < 2; ++mt) {
            uint32_t off = (uint32_t)(((mrow + mt * 16 + a_row) * LDA + kb + a_koff) * 2);
            ldsm4(aLo + off, al[mt]);
        }
#pragma unroll
        for (int p = 0; p < 2; ++p)
#pragma unroll
            for (int h = 0; h < 2; ++h)
#pragma unroll
                for (int mt = 0; mt < 2; ++mt)
                    mma16816(d[mt][p * 2 + h], al[mt], bh[p][2 * h], bh[p][2 * h + 1]);
    }
}

__global__ __launch_bounds__(ETHREADS, 1)
void edge_mlp_mma_kernel(const float* __restrict__ x, const int* __restrict__ ei,
                         const unsigned char* __restrict__ w1hi, const unsigned char* __restrict__ w1lo,
                         const unsigned char* __restrict__ w2hi, const unsigned char* __restrict__ w2lo,
                         const float* __restrict__ b1, const float* __restrict__ b2,
                         float* __restrict__ agg)
{
    extern __shared__ char smc[];
    int*   colS = (int*)(smc + SM_COLS);
    float* b1s  = (float*)(smc + SM_B1);
    float* b2s  = (float*)(smc + SM_B2);

    const int tid  = threadIdx.x;
    const int warp = tid >> 5;
    const int lane = tid & 31;

    const uint32_t sbase = smem_u32(smc);
    const uint32_t aHi  = sbase + A_HI_OFF,  aLo  = sbase + A_LO_OFF;
    const uint32_t w1Hi = sbase + W1_HI_OFF, w1Lo = sbase + W1_LO_OFF;
    const uint32_t w2Hi = sbase + W2_HI_OFF, w2Lo = sbase + W2_LO_OFF;

    // ---- load ALL weight tiles + biases once per CTA ----
    {
        uint4* d1h = (uint4*)(smc + W1_HI_OFF);
        uint4* d1l = (uint4*)(smc + W1_LO_OFF);
        uint4* d2h = (uint4*)(smc + W2_HI_OFF);
        uint4* d2l = (uint4*)(smc + W2_LO_OFF);
        const uint4* s1h = (const uint4*)w1hi;
        const uint4* s1l = (const uint4*)w1lo;
        const uint4* s2h = (const uint4*)w2hi;
        const uint4* s2l = (const uint4*)w2lo;
        for (int i = tid; i < WTILE_BYTES / 16; i += ETHREADS) {
            d1h[i] = s1h[i]; d1l[i] = s1l[i];
            d2h[i] = s2h[i]; d2l[i] = s2l[i];
        }
        if (tid < 128) { b1s[tid] = b1[tid]; b2s[tid] = b2[tid]; }
    }

    const int mrow = (warp >> 2) * 32;   // 4 warps down M
    const int ncol = (warp & 3) * 32;    // 4 warps across N
    const int crow = lane >> 2;
    const int ccol = (lane & 3) * 2;

    __syncthreads();

    // ---- grid-stride over edge tiles ----
    for (int t = blockIdx.x; t < NTILES; t += gridDim.x) {
        const int e0 = t * 128;

        // gather 128 edge-source rows, split to bf16 hi/lo (8 indep LDG chains)
#pragma unroll
        for (int rr = 0; rr < 8; ++rr) {
            const int r = warp + rr * 16;
            int e = e0 + r;
            float4 v = make_float4(0.f, 0.f, 0.f, 0.f);
            if (e < N_EDGES) {
                if (lane == 0) colS[r] = ei[N_EDGES + e];
                v = *((const float4*)(x + (size_t)ei[e] * D) + lane);
            } else if (lane == 0) colS[r] = -1;
            float vv[4] = {v.x, v.y, v.z, v.w};
            unsigned short h[4], lo[4];
#pragma unroll
            for (int q = 0; q < 4; ++q) {
                __nv_bfloat16 hh = __float2bfloat16_rn(vv[q]);
                float rr2 = vv[q] - __bfloat162float(hh);
                h[q]  = __bfloat16_as_ushort(hh);
                lo[q] = __bfloat16_as_ushort(__float2bfloat16_rn(rr2));
            }
            uint32_t o = (uint32_t)(r * LDA + lane * 4) * 2;
            *(uint2*)(smc + A_HI_OFF + o) = make_uint2(((uint32_t)h[1] << 16) | h[0],
                                                       ((uint32_t)h[3] << 16) | h[2]);
            *(uint2*)(smc + A_LO_OFF + o) = make_uint2(((uint32_t)lo[1] << 16) | lo[0],
                                                       ((uint32_t)lo[3] << 16) | lo[2]);
        }
        __syncthreads();

        float d[2][4][4];
#pragma unroll
        for (int mt = 0; mt < 2; ++mt)
#pragma unroll
            for (int nt = 0; nt < 4; ++nt)
#pragma unroll
                for (int q = 0; q < 4; ++q) d[mt][nt][q] = 0.f;

        // GEMM1: D1 = A @ W1 (3-term split)
        gemm_split32(aHi, aLo, w1Hi, w1Lo, mrow, ncol, lane, d);

        __syncthreads();   // all warps done reading A before T overwrites it

        // Epilogue 1: bias+relu, re-split, T -> A smem buffers
#pragma unroll
        for (int mt = 0; mt < 2; ++mt) {
#pragma unroll
            for (int nt = 0; nt < 4; ++nt) {
                const int row = mrow + mt * 16 + crow;
                const int col = ncol + nt * 8 + ccol;
                float f0 = fmaxf(d[mt][nt][0] + b1s[col],     0.f);
                float f1 = fmaxf(d[mt][nt][1] + b1s[col + 1], 0.f);
                float f2 = fmaxf(d[mt][nt][2] + b1s[col],     0.f);
                float f3 = fmaxf(d[mt][nt][3] + b1s[col + 1], 0.f);
                uint32_t o0 = (uint32_t)(row * LDA + col) * 2;
                uint32_t o1 = (uint32_t)((row + 8) * LDA + col) * 2;
                *(uint32_t*)(smc + A_HI_OFF + o0) = pack_bf16_hi(f0, f1);
                *(uint32_t*)(smc + A_HI_OFF + o1) = pack_bf16_hi(f2, f3);
                float r0 = f0 - __bfloat162float(__float2bfloat16_rn(f0));
                float r1 = f1 - __bfloat162float(__float2bfloat16_rn(f1));
                float r2 = f2 - __bfloat162float(__float2bfloat16_rn(f2));
                float r3 = f3 - __bfloat162float(__float2bfloat16_rn(f3));
                *(uint32_t*)(smc + A_LO_OFF + o0) = pack_bf16_hi(r0, r1);
                *(uint32_t*)(smc + A_LO_OFF + o1) = pack_bf16_hi(r2, r3);
            }
        }
        __syncthreads();   // T visible to all warps

#pragma unroll
        for (int mt = 0; mt < 2; ++mt)
#pragma unroll
            for (int nt = 0; nt < 4; ++nt)
#pragma unroll
                for (int q = 0; q < 4; ++q) d[mt][nt][q] = 0.f;

        // GEMM2: D2 = T @ W2
        gemm_split32(aHi, aLo, w2Hi, w2Lo, mrow, ncol, lane, d);

        __syncthreads();   // all warps done reading A before next tile's gather

        // Epilogue 2: bias + red.v2 scatter into agg[col] (registers only)
#pragma unroll
        for (int mt = 0; mt < 2; ++mt) {
            const int row0 = mrow + mt * 16 + crow;
            const int c0 = colS[row0];
            const int c1 = colS[row0 + 8];
#pragma unroll
            for (int nt = 0; nt < 4; ++nt) {
                const int col = ncol + nt * 8 + ccol;
                if (c0 >= 0)
                    red_add_v2(agg + (size_t)c0 * D + col,
                               d[mt][nt][0] + b2s[col], d[mt][nt][1] + b2s[col + 1]);
                if (c1 >= 0)
                    red_add_v2(agg + (size_t)c1 * D + col,
                               d[mt][nt][2] + b2s[col], d[mt][nt][3] + b2s[col + 1]);
            }
        }
        // colS is re-written next iteration only after the gather sync,
        // and scatter reads it before that sync -> safe.
    }
}

// ===========================================================================
// Node MLP (FFMA; occupancy 2)
// ===========================================================================
__global__ __launch_bounds__(256, 2)
void node_mlp_kernel(const float* __restrict__ x,
                     const float* __restrict__ agg,
                     const float* __restrict__ cnt,
                     const float* __restrict__ u,
                     const int* __restrict__ batch,
                     const float* __restrict__ w1, const float* __restrict__ b1,
                     const float* __restrict__ w2, const float* __restrict__ b2,
                     float* __restrict__ xout,
                     float* __restrict__ xsum)
{
    extern __shared__ float sm[];
    float* Hc  = sm;                       // [128][HPAD]
    float* Ws  = Hc + 128 * HPAD;          // [32][128]
    float* Ts  = Ws + 32 * 128;            // [128][EPAD]
    float* rcp = Ts + 128 * EPAD;          // [128]
    int*   bat = (int*)(rcp + 128);        // [128]

    const int tid = threadIdx.x;
    const int tx  = tid & 15;
    const int ty  = tid >> 4;
    const int n0  = blockIdx.x * 128;

    if (tid < 128) {
        int n = n0 + tid;
        if (n < N_NODES) {
            rcp[tid] = 1.0f / fmaxf(cnt[n], 1.0f);
            bat[tid] = batch[n];
        } else {
            rcp[tid] = 0.f;
            bat[tid] = 0;
        }
    }
    __syncthreads();

    float acc[8][8];
#pragma unroll
    for (int i = 0; i < 8; ++i)
#pragma unroll
        for (int j = 0; j < 8; ++j) acc[i][j] = 0.f;

    for (int kk = 0; kk < 384; kk += 32) {
        if (kk < 128) {
            for (int idx = tid; idx < 128 * 32; idx += 256) {
                int r = idx >> 5, k = idx & 31, n = n0 + r;
                Hc[r * HPAD + k] = (n < N_NODES) ? x[(size_t)n * D + kk + k] : 0.f;
            }
        } else if (kk < 256) {
            for (int idx = tid; idx < 128 * 32; idx += 256) {
                int r = idx >> 5, k = idx & 31, n = n0 + r;
                Hc[r * HPAD + k] = (n < N_NODES) ? agg[(size_t)n * D + (kk - 128) + k] * rcp[r] : 0.f;
            }
        } else {
            for (int idx = tid; idx < 128 * 32; idx += 256) {
                int r = idx >> 5, k = idx & 31, n = n0 + r;
                Hc[r * HPAD + k] = (n < N_NODES) ? u[bat[r] * D + (kk - 256) + k] : 0.f;
            }
        }
#pragma unroll 4
        for (int idx = tid; idx < 32 * 128; idx += 256) Ws[idx] = w1[kk * 128 + idx];
        __syncthreads();
#pragma unroll 4
        for (int k = 0; k < 32; ++k) {
            float ra[8];
#pragma unroll
            for (int i = 0; i < 8; ++i) ra[i] = Hc[(ty * 8 + i) * HPAD + k];
            float4 rb0 = *(const float4*)&Ws[k * 128 + tx * 8];
            float4 rb1 = *(const float4*)&Ws[k * 128 + tx * 8 + 4];
            float rb[8] = {rb0.x, rb0.y, rb0.z, rb0.w, rb1.x, rb1.y, rb1.z, rb1.w};
#pragma unroll
            for (int i = 0; i < 8; ++i)
#pragma unroll
                for (int j = 0; j < 8; ++j) acc[i][j] = fmaf(ra[i], rb[j], acc[i][j]);
        }
        __syncthreads();
    }

    {
        float bv[8];
#pragma unroll
        for (int j = 0; j < 8; ++j) bv[j] = b1[tx * 8 + j];
#pragma unroll
        for (int i = 0; i < 8; ++i) {
#pragma unroll
            for (int j = 0; j < 8; ++j) acc[i][j] = fmaxf(acc[i][j] + bv[j], 0.f);
            *(float4*)&Ts[(ty * 8 + i) * EPAD + tx * 8]     = make_float4(acc[i][0], acc[i][1], acc[i][2], acc[i][3]);
            *(float4*)&Ts[(ty * 8 + i) * EPAD + tx * 8 + 4] = make_float4(acc[i][4], acc[i][5], acc[i][6], acc[i][7]);
        }
    }

#pragma unroll
    for (int i = 0; i < 8; ++i)
#pragma unroll
        for (int j = 0; j < 8; ++j) acc[i][j] = 0.f;

    for (int kk = 0; kk < D; kk += 32) {
#pragma unroll 4
        for (int idx = tid; idx < 32 * 128; idx += 256) Ws[idx] = w2[kk * 128 + idx];
        __syncthreads();
#pragma unroll 4
        for (int k = 0; k < 32; ++k) {
            float ra[8];
#pragma unroll
            for (int i = 0; i < 8; ++i) ra[i] = Ts[(ty * 8 + i) * EPAD + kk + k];
            float4 rb0 = *(const float4*)&Ws[k * 128 + tx * 8];
            float4 rb1 = *(const float4*)&Ws[k * 128 + tx * 8 + 4];
            float rb[8] = {rb0.x, rb0.y, rb0.z, rb0.w, rb1.x, rb1.y, rb1.z, rb1.w};
#pragma unroll
            for (int i = 0; i < 8; ++i)
#pragma unroll
                for (int j = 0; j < 8; ++j) acc[i][j] = fmaf(ra[i], rb[j], acc[i][j]);
        }
        __syncthreads();
    }

    {
        float bv[8];
#pragma unroll
        for (int j = 0; j < 8; ++j) bv[j] = b2[tx * 8 + j];
#pragma unroll
        for (int i = 0; i < 8; ++i) {
            int r = ty * 8 + i;
            int n = n0 + r;
            if (n < N_NODES) {
                float o[8];
#pragma unroll
                for (int j = 0; j < 8; ++j) o[j] = acc[i][j] + bv[j];
                *(float4*)&xout[(size_t)n * D + tx * 8]     = make_float4(o[0], o[1], o[2], o[3]);
                *(float4*)&xout[(size_t)n * D + tx * 8 + 4] = make_float4(o[4], o[5], o[6], o[7]);
                float* sbase = xsum + (size_t)bat[r] * D + tx * 8;
                red_add_v4(sbase,     o[0], o[1], o[2], o[3]);
                red_add_v4(sbase + 4, o[4], o[5], o[6], o[7]);
            }
        }
    }
}

// ===========================================================================
// Global MLP (unchanged)
// ===========================================================================
__global__ __launch_bounds__(256, 1)
void global_mlp_kernel(const float* __restrict__ u,
                       const float* __restrict__ xsum,
                       const float* __restrict__ bcnt,
                       const float* __restrict__ w1, const float* __restrict__ b1,
                       const float* __restrict__ w2, const float* __restrict__ b2,
                       float* __restrict__ uout)
{
    extern __shared__ float sm[];
    float* G  = sm;              // [64][256]
    float* Hh = G + 64 * 256;    // [64][EPAD]

    const int tid = threadIdx.x;
    const int tx  = tid & 15;
    const int ty  = tid >> 4;

    for (int idx = tid; idx < 64 * 128; idx += 256) {
        int b = idx >> 7, c = idx & 127;
        G[b * 256 + c]       = u[idx];
        G[b * 256 + 128 + c] = xsum[idx] / fmaxf(bcnt[b], 1.0f);
    }
    __syncthreads();

    float acc[4][8];
#pragma unroll
    for (int i = 0; i < 4; ++i)
#pragma unroll
        for (int j = 0; j < 8; ++j) acc[i][j] = 0.f;

#pragma unroll 4
    for (int k = 0; k < 256; ++k) {
        float ra[4];
#pragma unroll
        for (int i = 0; i < 4; ++i) ra[i] = G[(ty * 4 + i) * 256 + k];
        float4 rb0 = __ldg((const float4*)&w1[k * 128 + tx * 8]);
        float4 rb1 = __ldg((const float4*)&w1[k * 128 + tx * 8 + 4]);
        float rb[8] = {rb0.x, rb0.y, rb0.z, rb0.w, rb1.x, rb1.y, rb1.z, rb1.w};
#pragma unroll
        for (int i = 0; i < 4; ++i)
#pragma unroll
            for (int j = 0; j < 8; ++j) acc[i][j] = fmaf(ra[i], rb[j], acc[i][j]);
    }

    {
        float bv[8];
#pragma unroll
        for (int j = 0; j < 8; ++j) bv[j] = b1[tx * 8 + j];
#pragma unroll
        for (int i = 0; i < 4; ++i) {
#pragma unroll
            for (int j = 0; j < 8; ++j) acc[i][j] = fmaxf(acc[i][j] + bv[j], 0.f);
            *(float4*)&Hh[(ty * 4 + i) * EPAD + tx * 8]     = make_float4(acc[i][0], acc[i][1], acc[i][2], acc[i][3]);
            *(float4*)&Hh[(ty * 4 + i) * EPAD + tx * 8 + 4] = make_float4(acc[i][4], acc[i][5], acc[i][6], acc[i][7]);
        }
    }
    __syncthreads();

#pragma unroll
    for (int i = 0; i < 4; ++i)
#pragma unroll
        for (int j = 0; j < 8; ++j) acc[i][j] = 0.f;

#pragma unroll 4
    for (int k = 0; k < 128; ++k) {
        float ra[4];
#pragma unroll
        for (int i = 0; i < 4; ++i) ra[i] = Hh[(ty * 4 + i) * EPAD + k];
        float4 rb0 = __ldg((const float4*)&w2[k * 128 + tx * 8]);
        float4 rb1 = __ldg((const float4*)&w2[k * 128 + tx * 8 + 4]);
        float rb[8] = {rb0.x, rb0.y, rb0.z, rb0.w, rb1.x, rb1.y, rb1.z, rb1.w};
#pragma unroll
        for (int i = 0; i < 4; ++i)
#pragma unroll
            for (int j = 0; j < 8; ++j) acc[i][j] = fmaf(ra[i], rb[j], acc[i][j]);
    }

    {
        float bv[8];
#pragma unroll
        for (int j = 0; j < 8; ++j) bv[j] = b2[tx * 8 + j];
#pragma unroll
        for (int i = 0; i < 4; ++i) {
            int b = ty * 4 + i;
            *(float4*)&uout[b * D + tx * 8]     = make_float4(acc[i][0] + bv[0], acc[i][1] + bv[1],
                                                              acc[i][2] + bv[2], acc[i][3] + bv[3]);
            *(float4*)&uout[b * D + tx * 8 + 4] = make_float4(acc[i][4] + bv[4], acc[i][5] + bv[5],
                                                              acc[i][6] + bv[6], acc[i][7] + bv[7]);
        }
    }
}

// ===========================================================================
// Host side
// ===========================================================================
static const int NODE_SMEM = (128 * HPAD + 32 * 128 + 128 * EPAD + 128) * 4 + 128 * 4;
static const int GLOB_SMEM = (64 * 256 + 64 * EPAD) * 4;
#define EDGE_GRID 148

extern "C" void kernel_launch(void* const* d_in, const int* in_sizes, int n_in,
                              void* d_out, int out_size) {
    const float* x0    = (const float*)d_in[0];
    const int*   ei    = (const int*)d_in[1];      // int32 (JAX x64 disabled)
    const float* u0    = (const float*)d_in[2];
    const int*   batch = (const int*)d_in[3];      // int32
    const float* n1w1 = (const float*)d_in[4];
    const float* n1b1 = (const float*)d_in[5];
    const float* n1w2 = (const float*)d_in[6];
    const float* n1b2 = (const float*)d_in[7];
    const float* n2w1 = (const float*)d_in[8];
    const float* n2b1 = (const float*)d_in[9];
    const float* n2w2 = (const float*)d_in[10];
    const float* n2b2 = (const float*)d_in[11];
    const float* gw1  = (const float*)d_in[12];
    const float* gb1  = (const float*)d_in[13];
    const float* gw2  = (const float*)d_in[14];
    const float* gb2  = (const float*)d_in[15];
    float* out = (float*)d_out;

    float *px, *pu, *pagg, *pcnt, *pxsum, *pbcnt;
    unsigned char* pwt;
    cudaGetSymbolAddress((void**)&px,    g_x);
    cudaGetSymbolAddress((void**)&pu,    g_u);
    cudaGetSymbolAddress((void**)&pagg,  g_agg);
    cudaGetSymbolAddress((void**)&pcnt,  g_cnt);
    cudaGetSymbolAddress((void**)&pxsum, g_xsum);
    cudaGetSymbolAddress((void**)&pbcnt, g_bcnt);
    cudaGetSymbolAddress((void**)&pwt,   g_wt);
    float* xbuf[2] = {px, px + (size_t)N_NODES * D};
    float* ubuf[2] = {pu, pu + (size_t)NB * D};

    cudaFuncSetAttribute(edge_mlp_mma_kernel, cudaFuncAttributeMaxDynamicSharedMemorySize, EDGE_SMEM);
    cudaFuncSetAttribute(node_mlp_kernel,     cudaFuncAttributeMaxDynamicSharedMemorySize, NODE_SMEM);
    cudaFuncSetAttribute(global_mlp_kernel,   cudaFuncAttributeMaxDynamicSharedMemorySize, GLOB_SMEM);

    // one-time per launch: counts + weight tiles
    cudaMemsetAsync(pcnt,  0, N_NODES * sizeof(float));
    cudaMemsetAsync(pbcnt, 0, NB * sizeof(float));
    count_edges_kernel<<<(N_EDGES + 255) / 256, 256>>>(ei, pcnt);
    count_batch_kernel<<<(N_NODES + 255) / 256, 256>>>(batch, pbcnt);
    prep_weights_kernel<<<2 * NLAYERS, 256>>>(n1w1, n1w2);

    const float* xc = x0;
    const float* uc = u0;
    for (int l = 0; l < NLAYERS; ++l) {
        cudaMemsetAsync(pagg,  0, (size_t)N_NODES * D * sizeof(float));
        cudaMemsetAsync(pxsum, 0, (size_t)NB * D * sizeof(float));

        const unsigned char* w1hi = pwt + (size_t)(l * 4 + 0) * WTILE_BYTES;
        const unsigned char* w1lo = pwt + (size_t)(l * 4 + 1) * WTILE_BYTES;
        const unsigned char* w2hi = pwt + (size_t)(l * 4 + 2) * WTILE_BYTES;
        const unsigned char* w2lo = pwt + (size_t)(l * 4 + 3) * WTILE_BYTES;

        edge_mlp_mma_kernel<<<EDGE_GRID, ETHREADS, EDGE_SMEM>>>(
            xc, ei, w1hi, w1lo, w2hi, w2lo,
            n1b1 + (size_t)l * D, n1b2 + (size_t)l * D, pagg);

        float* xn = (l == NLAYERS - 1) ? out : xbuf[l & 1];
        node_mlp_kernel<<<(N_NODES + 127) / 128, 256, NODE_SMEM>>>(
            xc, pagg, pcnt, uc, batch,
            n2w1 + (size_t)l * 384 * D, n2b1 + (size_t)l * D,
            n2w2 + (size_t)l * D * D,   n2b2 + (size_t)l * D,
            xn, pxsum);

        float* un = (l == NLAYERS - 1) ? out + (size_t)N_NODES * D : ubuf[l & 1];
        global_mlp_kernel<<<1, 256, GLOB_SMEM>>>(
            uc, pxsum, pbcnt,
            gw1 + (size_t)l * 256 * D, gb1 + (size_t)l * D,
            gw2 + (size_t)l * D * D,   gb2 + (size_t)l * D,
            un);

        xc = xn;
        uc = un;
    }
}

// round 13
// speedup vs baseline: 1.0502x; 1.0502x over previous
#include <cuda_runtime.h>
#include <cuda_bf16.h>
#include <cstdint>

#define N_NODES 50000
#define N_EDGES 600000
#define NB      64
#define D       128      // F == H == U
#define NLAYERS 4

#define EPAD 132   // padded row stride for 128-wide smem tiles (node/global)
#define HPAD 36    // padded row stride for 32-wide K chunks (node)

#define LDA 136                      // bf16 row stride for mma tiles (272B, 16B-aligned)
#define WTILE_BYTES (128 * LDA * 2)  // 34816 bytes per 128x128 bf16 tile
#define ATILE_BYTES (64 * LDA * 2)   // 17408 bytes per 64x128 bf16 tile
#define NT64 (N_EDGES / 64)          // 9375 edge tiles, exact

// ===========================================================================
// Scratch (no allocations allowed -> __device__ globals)
// ===========================================================================
__device__ float g_x[2][N_NODES * D];
__device__ float g_u[2][NB * D];
__device__ float g_agg[N_NODES * D];
__device__ float g_cnt[N_NODES];
__device__ float g_xsum[NB * D];
__device__ float g_bcnt[NB];
// current-layer x pre-split into bf16 hi/lo (node-major) for cp.async gather
__device__ __align__(16) __nv_bfloat16 g_xhi[N_NODES * D];
__device__ __align__(16) __nv_bfloat16 g_xlo[N_NODES * D];
// transposed/split bf16 weight tiles [n][k], padded LDA: [layer][w1,w2][hi,lo]
__device__ __align__(16) unsigned char g_wt[16 * WTILE_BYTES];

__device__ __forceinline__ void red_add_v4(float* addr, float a, float b, float c, float d) {
    asm volatile("red.global.add.v4.f32 [%0], {%1,%2,%3,%4};"
                 :: "l"(addr), "f"(a), "f"(b), "f"(c), "f"(d) : "memory");
}
__device__ __forceinline__ void red_add_v2(float* addr, float a, float b) {
    asm volatile("red.global.add.v2.f32 [%0], {%1,%2};"
                 :: "l"(addr), "f"(a), "f"(b) : "memory");
}

__device__ __forceinline__ uint32_t smem_u32(const void* p) {
    uint32_t a;
    asm("{ .reg .u64 t; cvta.to.shared.u64 t, %1; cvt.u32.u64 %0, t; }" : "=r"(a) : "l"(p));
    return a;
}

__device__ __forceinline__ void ldsm4(uint32_t addr, uint32_t r[4]) {
    asm volatile("ldmatrix.sync.aligned.m8n8.x4.shared.b16 {%0,%1,%2,%3}, [%4];"
                 : "=r"(r[0]), "=r"(r[1]), "=r"(r[2]), "=r"(r[3]) : "r"(addr));
}

__device__ __forceinline__ void mma16816(float d[4], const uint32_t a[4],
                                         uint32_t b0, uint32_t b1) {
    asm volatile(
        "mma.sync.aligned.m16n8k16.row.col.f32.bf16.bf16.f32 "
        "{%0,%1,%2,%3}, {%4,%5,%6,%7}, {%8,%9}, {%0,%1,%2,%3};"
        : "+f"(d[0]), "+f"(d[1]), "+f"(d[2]), "+f"(d[3])
        : "r"(a[0]), "r"(a[1]), "r"(a[2]), "r"(a[3]), "r"(b0), "r"(b1));
}

__device__ __forceinline__ uint32_t pack_bf16_hi(float f0, float f1) {
    return ((uint32_t)__bfloat16_as_ushort(__float2bfloat16_rn(f1)) << 16)
         |  (uint32_t)__bfloat16_as_ushort(__float2bfloat16_rn(f0));
}

#define CP_ASYNC16(dst, src) \
    asm volatile("cp.async.ca.shared.global [%0], [%1], 16;" :: "r"(dst), "l"(src) : "memory")
#define CP_ASYNC4(dst, src) \
    asm volatile("cp.async.ca.shared.global [%0], [%1], 4;"  :: "r"(dst), "l"(src) : "memory")
#define CP_COMMIT() asm volatile("cp.async.commit_group;" ::: "memory")
#define CP_WAIT0()  asm volatile("cp.async.wait_group 0;"  ::: "memory")

// ===========================================================================
// One-time kernels
// ===========================================================================
__global__ void count_edges_kernel(const int* __restrict__ ei, float* __restrict__ cnt) {
    int e = blockIdx.x * 256 + threadIdx.x;
    if (e < N_EDGES) atomicAdd(&cnt[ei[N_EDGES + e]], 1.0f);
}
__global__ void count_batch_kernel(const int* __restrict__ batch, float* __restrict__ bcnt) {
    int n = blockIdx.x * 256 + threadIdx.x;
    if (n < N_NODES) atomicAdd(&bcnt[batch[n]], 1.0f);
}

// Split layer-0 x into bf16 hi/lo (2 elems per thread)
__global__ void split_x_kernel(const float* __restrict__ x) {
    int i = blockIdx.x * 256 + threadIdx.x;
    if (i < N_NODES * (D / 2)) {
        float2 v = ((const float2*)x)[i];
        ((uint32_t*)g_xhi)[i] = pack_bf16_hi(v.x, v.y);
        float l0 = v.x - __bfloat162float(__float2bfloat16_rn(v.x));
        float l1 = v.y - __bfloat162float(__float2bfloat16_rn(v.y));
        ((uint32_t*)g_xlo)[i] = pack_bf16_hi(l0, l1);
    }
}

// Transpose+split W (row-major [K=128, N=128]) into bf16 hi/lo tiles [n][k], LDA pad.
__global__ void prep_weights_kernel(const float* __restrict__ n1w1,
                                    const float* __restrict__ n1w2) {
    int b = blockIdx.x;                 // 0..7: (layer, w1/w2)
    int l = b >> 1, which = b & 1;
    const float* w = (which ? n1w2 : n1w1) + (size_t)l * D * D;
    unsigned char* thi = g_wt + ((size_t)b * 2 + 0) * WTILE_BYTES;
    unsigned char* tlo = g_wt + ((size_t)b * 2 + 1) * WTILE_BYTES;
    for (int idx = threadIdx.x; idx < 128 * 32; idx += 256) {
        int n = idx >> 5, kq = (idx & 31) << 2;
        unsigned short hh[4], ll[4];
#pragma unroll
        for (int q = 0; q < 4; ++q) {
            float f = w[(kq + q) * D + n];
            __nv_bfloat16 h = __float2bfloat16_rn(f);
            float r = f - __bfloat162float(h);
            hh[q] = __bfloat16_as_ushort(h);
            ll[q] = __bfloat16_as_ushort(__float2bfloat16_rn(r));
        }
        uint32_t o = (uint32_t)(n * LDA + kq) * 2;
        *(uint2*)(thi + o) = make_uint2(((uint32_t)hh[1] << 16) | hh[0],
                                        ((uint32_t)hh[3] << 16) | hh[2]);
        *(uint2*)(tlo + o) = make_uint2(((uint32_t)ll[1] << 16) | ll[0],
                                        ((uint32_t)ll[3] << 16) | ll[2]);
    }
}

// ===========================================================================
// Edge MLP via mma.sync (split-bf16, 3-term), persistent CTAs,
// resident weights, DOUBLE-BUFFERED 64-row tiles with cp.async prefetch.
// smem: [colS 2x64][b1][b2] | A(hi,lo) x2 bufs | W1(hi,lo) W2(hi,lo)
// ===========================================================================
#define SM_COLS   0                               // int[2][64]
#define SM_B1     512                             // float[128]
#define SM_B2     1024                            // float[128]
#define A_OFF     2048                            // 4 x ATILE (buf0 hi,lo / buf1 hi,lo)
#define W1_HI_OFF (A_OFF + 4 * ATILE_BYTES)       // 71680
#define W1_LO_OFF (W1_HI_OFF + WTILE_BYTES)
#define W2_HI_OFF (W1_LO_OFF + WTILE_BYTES)
#define W2_LO_OFF (W2_HI_OFF + WTILE_BYTES)
static const int EDGE_SMEM = W2_LO_OFF + WTILE_BYTES;   // 210944
#define ETHREADS 512
#define EDGE_GRID 148

// Issue cp.async gather of one 64-edge tile into buffer `buf`.
// 8 threads per row; each copies 32B of hi and 32B of lo.
__device__ __forceinline__ void prefetch_tile(int t, int buf, int tid,
                                              uint32_t sbase,
                                              const int* __restrict__ ei) {
    if (t >= NT64) return;
    const int e0 = t * 64;
    if (tid < 64)
        CP_ASYNC4(sbase + SM_COLS + buf * 256 + tid * 4,
                  (const char*)(ei + N_EDGES + e0 + tid));
    const int r = tid >> 3;
    const int c = (tid & 7) * 32;          // byte offset within 256B row
    const int src = ei[e0 + r];
    const char* sh = (const char*)(g_xhi + (size_t)src * D) + c;
    const char* sl = (const char*)(g_xlo + (size_t)src * D) + c;
    const uint32_t dh = sbase + A_OFF + buf * 2 * ATILE_BYTES + r * (LDA * 2) + c;
    const uint32_t dl = dh + ATILE_BYTES;
    CP_ASYNC16(dh,      sh);
    CP_ASYNC16(dh + 16, sh + 16);
    CP_ASYNC16(dl,      sl);
    CP_ASYNC16(dl + 16, sl + 16);
}

// One split GEMM pass over K=128 on a 64xN tile: D += Ahi@Whi + Ahi@Wlo + Alo@Whi.
// Warp tile 32x16: d[2 m16][2 n8][4].
__device__ __forceinline__ void gemm_split64(uint32_t aHi, uint32_t aLo,
                                             uint32_t wHi, uint32_t wLo,
                                             int mrow, int ncol, int lane,
                                             float d[2][2][4]) {
    const int a_row  = lane & 15;
    const int a_koff = (lane >> 4) << 3;
    const int b_row  = ncol + ((lane >> 4) << 3) + (lane & 7);
    const int b_koff = ((lane >> 3) & 1) << 3;
#pragma unroll
    for (int ks = 0; ks < 8; ++ks) {
        const int kb = ks * 16;
        uint32_t ah[2][4], al[2][4], bh[4], bl[4];
#pragma unroll
        for (int mt = 0; mt < 2; ++mt) {
            uint32_t off = (uint32_t)(((mrow + mt * 16 + a_row) * LDA + kb + a_koff) * 2);
            ldsm4(aHi + off, ah[mt]);
            ldsm4(aLo + off, al[mt]);
        }
        {
            uint32_t off = (uint32_t)((b_row * LDA + kb + b_koff) * 2);
            ldsm4(wHi + off, bh);
            ldsm4(wLo + off, bl);
        }
#pragma unroll
        for (int nt = 0; nt < 2; ++nt)
#pragma unroll
            for (int mt = 0; mt < 2; ++mt) {
                mma16816(d[mt][nt], ah[mt], bh[2 * nt], bh[2 * nt + 1]);
                mma16816(d[mt][nt], ah[mt], bl[2 * nt], bl[2 * nt + 1]);
                mma16816(d[mt][nt], al[mt], bh[2 * nt], bh[2 * nt + 1]);
            }
    }
}

__global__ __launch_bounds__(ETHREADS, 1)
void edge_mlp_mma_kernel(const int* __restrict__ ei,
                         const unsigned char* __restrict__ w1hi, const unsigned char* __restrict__ w1lo,
                         const unsigned char* __restrict__ w2hi, const unsigned char* __restrict__ w2lo,
                         const float* __restrict__ b1, const float* __restrict__ b2,
                         float* __restrict__ agg)
{
    extern __shared__ char smc[];
    float* b1s = (float*)(smc + SM_B1);
    float* b2s = (float*)(smc + SM_B2);

    const int tid  = threadIdx.x;
    const int warp = tid >> 5;
    const int lane = tid & 31;

    const uint32_t sbase = smem_u32(smc);
    const uint32_t w1Hi = sbase + W1_HI_OFF, w1Lo = sbase + W1_LO_OFF;
    const uint32_t w2Hi = sbase + W2_HI_OFF, w2Lo = sbase + W2_LO_OFF;

    // ---- load ALL weight tiles + biases once per CTA ----
    {
        uint4* d1h = (uint4*)(smc + W1_HI_OFF);
        uint4* d1l = (uint4*)(smc + W1_LO_OFF);
        uint4* d2h = (uint4*)(smc + W2_HI_OFF);
        uint4* d2l = (uint4*)(smc + W2_LO_OFF);
        const uint4* s1h = (const uint4*)w1hi;
        const uint4* s1l = (const uint4*)w1lo;
        const uint4* s2h = (const uint4*)w2hi;
        const uint4* s2l = (const uint4*)w2lo;
        for (int i = tid; i < WTILE_BYTES / 16; i += ETHREADS) {
            d1h[i] = s1h[i]; d1l[i] = s1l[i];
            d2h[i] = s2h[i]; d2l[i] = s2l[i];
        }
        if (tid < 128) { b1s[tid] = b1[tid]; b2s[tid] = b2[tid]; }
    }

    const int mrow = (warp >> 3) * 32;   // 2 warp-groups down M (64 rows)
    const int ncol = (warp & 7) * 16;    // 8 warps across N (128 cols)
    const int crow = lane >> 2;
    const int ccol = (lane & 3) * 2;

    // ---- pipeline prologue: prefetch first tile ----
    int t = blockIdx.x;
    int buf = 0;
    prefetch_tile(t, 0, tid, sbase, ei);
    CP_COMMIT();

    for (; t < NT64; t += EDGE_GRID, buf ^= 1) {
        CP_WAIT0();
        __syncthreads();   // buffer `buf` (A + colS) visible to all threads

        // prefetch next tile into the other buffer; overlaps with compute below
        prefetch_tile(t + EDGE_GRID, buf ^ 1, tid, sbase, ei);
        CP_COMMIT();

        const uint32_t aHi = sbase + A_OFF + buf * 2 * ATILE_BYTES;
        const uint32_t aLo = aHi + ATILE_BYTES;
        const int* colSb = (const int*)(smc + SM_COLS + buf * 256);

        float d[2][2][4];
#pragma unroll
        for (int mt = 0; mt < 2; ++mt)
#pragma unroll
            for (int nt = 0; nt < 2; ++nt)
#pragma unroll
                for (int q = 0; q < 4; ++q) d[mt][nt][q] = 0.f;

        // GEMM1: D1 = A @ W1
        gemm_split64(aHi, aLo, w1Hi, w1Lo, mrow, ncol, lane, d);

        __syncthreads();   // all warps done reading A before T overwrites it

        // Epilogue 1: bias+relu, re-split, T -> A buffers (in place)
#pragma unroll
        for (int mt = 0; mt < 2; ++mt) {
#pragma unroll
            for (int nt = 0; nt < 2; ++nt) {
                const int row = mrow + mt * 16 + crow;
                const int col = ncol + nt * 8 + ccol;
                float f0 = fmaxf(d[mt][nt][0] + b1s[col],     0.f);
                float f1 = fmaxf(d[mt][nt][1] + b1s[col + 1], 0.f);
                float f2 = fmaxf(d[mt][nt][2] + b1s[col],     0.f);
                float f3 = fmaxf(d[mt][nt][3] + b1s[col + 1], 0.f);
                uint32_t o0 = (uint32_t)(row * LDA + col) * 2;
                uint32_t o1 = (uint32_t)((row + 8) * LDA + col) * 2;
                char* abase = smc + A_OFF + buf * 2 * ATILE_BYTES;
                *(uint32_t*)(abase + o0) = pack_bf16_hi(f0, f1);
                *(uint32_t*)(abase + o1) = pack_bf16_hi(f2, f3);
                float r0 = f0 - __bfloat162float(__float2bfloat16_rn(f0));
                float r1 = f1 - __bfloat162float(__float2bfloat16_rn(f1));
                float r2 = f2 - __bfloat162float(__float2bfloat16_rn(f2));
                float r3 = f3 - __bfloat162float(__float2bfloat16_rn(f3));
                *(uint32_t*)(abase + ATILE_BYTES + o0) = pack_bf16_hi(r0, r1);
                *(uint32_t*)(abase + ATILE_BYTES + o1) = pack_bf16_hi(r2, r3);
            }
        }
        __syncthreads();   // T visible to all warps

#pragma unroll
        for (int mt = 0; mt < 2; ++mt)
#pragma unroll
            for (int nt = 0; nt < 2; ++nt)
#pragma unroll
                for (int q = 0; q < 4; ++q) d[mt][nt][q] = 0.f;

        // GEMM2: D2 = T @ W2
        gemm_split64(aHi, aLo, w2Hi, w2Lo, mrow, ncol, lane, d);

        // Epilogue 2: bias + red.v2 scatter into agg[col]
        // (reads only registers + colS[buf]; next write to this buffer happens
        //  only after the next iteration's top __syncthreads -> safe)
#pragma unroll
        for (int mt = 0; mt < 2; ++mt) {
            const int row0 = mrow + mt * 16 + crow;
            const int c0 = colSb[row0];
            const int c1 = colSb[row0 + 8];
#pragma unroll
            for (int nt = 0; nt < 2; ++nt) {
                const int col = ncol + nt * 8 + ccol;
                red_add_v2(agg + (size_t)c0 * D + col,
                           d[mt][nt][0] + b2s[col], d[mt][nt][1] + b2s[col + 1]);
                red_add_v2(agg + (size_t)c1 * D + col,
                           d[mt][nt][2] + b2s[col], d[mt][nt][3] + b2s[col + 1]);
            }
        }
    }
}

// ===========================================================================
// Node MLP (FFMA; occupancy 2). Also emits bf16 hi/lo split of x' for the
// next layer's edge gather.
// ===========================================================================
__global__ __launch_bounds__(256, 2)
void node_mlp_kernel(const float* __restrict__ x,
                     const float* __restrict__ agg,
                     const float* __restrict__ cnt,
                     const float* __restrict__ u,
                     const int* __restrict__ batch,
                     const float* __restrict__ w1, const float* __restrict__ b1,
                     const float* __restrict__ w2, const float* __restrict__ b2,
                     float* __restrict__ xout,
                     float* __restrict__ xsum)
{
    extern __shared__ float sm[];
    float* Hc  = sm;                       // [128][HPAD]
    float* Ws  = Hc + 128 * HPAD;          // [32][128]
    float* Ts  = Ws + 32 * 128;            // [128][EPAD]
    float* rcp = Ts + 128 * EPAD;          // [128]
    int*   bat = (int*)(rcp + 128);        // [128]

    const int tid = threadIdx.x;
    const int tx  = tid & 15;
    const int ty  = tid >> 4;
    const int n0  = blockIdx.x * 128;

    if (tid < 128) {
        int n = n0 + tid;
        if (n < N_NODES) {
            rcp[tid] = 1.0f / fmaxf(cnt[n], 1.0f);
            bat[tid] = batch[n];
        } else {
            rcp[tid] = 0.f;
            bat[tid] = 0;
        }
    }
    __syncthreads();

    float acc[8][8];
#pragma unroll
    for (int i = 0; i < 8; ++i)
#pragma unroll
        for (int j = 0; j < 8; ++j) acc[i][j] = 0.f;

    for (int kk = 0; kk < 384; kk += 32) {
        if (kk < 128) {
            for (int idx = tid; idx < 128 * 32; idx += 256) {
                int r = idx >> 5, k = idx & 31, n = n0 + r;
                Hc[r * HPAD + k] = (n < N_NODES) ? x[(size_t)n * D + kk + k] : 0.f;
            }
        } else if (kk < 256) {
            for (int idx = tid; idx < 128 * 32; idx += 256) {
                int r = idx >> 5, k = idx & 31, n = n0 + r;
                Hc[r * HPAD + k] = (n < N_NODES) ? agg[(size_t)n * D + (kk - 128) + k] * rcp[r] : 0.f;
            }
        } else {
            for (int idx = tid; idx < 128 * 32; idx += 256) {
                int r = idx >> 5, k = idx & 31, n = n0 + r;
                Hc[r * HPAD + k] = (n < N_NODES) ? u[bat[r] * D + (kk - 256) + k] : 0.f;
            }
        }
#pragma unroll 4
        for (int idx = tid; idx < 32 * 128; idx += 256) Ws[idx] = w1[kk * 128 + idx];
        __syncthreads();
#pragma unroll 4
        for (int k = 0; k < 32; ++k) {
            float ra[8];
#pragma unroll
            for (int i = 0; i < 8; ++i) ra[i] = Hc[(ty * 8 + i) * HPAD + k];
            float4 rb0 = *(const float4*)&Ws[k * 128 + tx * 8];
            float4 rb1 = *(const float4*)&Ws[k * 128 + tx * 8 + 4];
            float rb[8] = {rb0.x, rb0.y, rb0.z, rb0.w, rb1.x, rb1.y, rb1.z, rb1.w};
#pragma unroll
            for (int i = 0; i < 8; ++i)
#pragma unroll
                for (int j = 0; j < 8; ++j) acc[i][j] = fmaf(ra[i], rb[j], acc[i][j]);
        }
        __syncthreads();
    }

    {
        float bv[8];
#pragma unroll
        for (int j = 0; j < 8; ++j) bv[j] = b1[tx * 8 + j];
#pragma unroll
        for (int i = 0; i < 8; ++i) {
#pragma unroll
            for (int j = 0; j < 8; ++j) acc[i][j] = fmaxf(acc[i][j] + bv[j], 0.f);
            *(float4*)&Ts[(ty * 8 + i) * EPAD + tx * 8]     = make_float4(acc[i][0], acc[i][1], acc[i][2], acc[i][3]);
            *(float4*)&Ts[(ty * 8 + i) * EPAD + tx * 8 + 4] = make_float4(acc[i][4], acc[i][5], acc[i][6], acc[i][7]);
        }
    }

#pragma unroll
    for (int i = 0; i < 8; ++i)
#pragma unroll
        for (int j = 0; j < 8; ++j) acc[i][j] = 0.f;

    for (int kk = 0; kk < D; kk += 32) {
#pragma unroll 4
        for (int idx = tid; idx < 32 * 128; idx += 256) Ws[idx] = w2[kk * 128 + idx];
        __syncthreads();
#pragma unroll 4
        for (int k = 0; k < 32; ++k) {
            float ra[8];
#pragma unroll
            for (int i = 0; i < 8; ++i) ra[i] = Ts[(ty * 8 + i) * EPAD + kk + k];
            float4 rb0 = *(const float4*)&Ws[k * 128 + tx * 8];
            float4 rb1 = *(const float4*)&Ws[k * 128 + tx * 8 + 4];
            float rb[8] = {rb0.x, rb0.y, rb0.z, rb0.w, rb1.x, rb1.y, rb1.z, rb1.w};
#pragma unroll
            for (int i = 0; i < 8; ++i)
#pragma unroll
                for (int j = 0; j < 8; ++j) acc[i][j] = fmaf(ra[i], rb[j], acc[i][j]);
        }
        __syncthreads();
    }

    {
        float bv[8];
#pragma unroll
        for (int j = 0; j < 8; ++j) bv[j] = b2[tx * 8 + j];
#pragma unroll
        for (int i = 0; i < 8; ++i) {
            int r = ty * 8 + i;
            int n = n0 + r;
            if (n < N_NODES) {
                float o[8];
#pragma unroll
                for (int j = 0; j < 8; ++j) o[j] = acc[i][j] + bv[j];
                *(float4*)&xout[(size_t)n * D + tx * 8]     = make_float4(o[0], o[1], o[2], o[3]);
                *(float4*)&xout[(size_t)n * D + tx * 8 + 4] = make_float4(o[4], o[5], o[6], o[7]);
                // bf16 hi/lo split for next layer's edge gather
                uint4 hv, lv;
                hv.x = pack_bf16_hi(o[0], o[1]); hv.y = pack_bf16_hi(o[2], o[3]);
                hv.z = pack_bf16_hi(o[4], o[5]); hv.w = pack_bf16_hi(o[6], o[7]);
                float lo[8];
#pragma unroll
                for (int j = 0; j < 8; ++j)
                    lo[j] = o[j] - __bfloat162float(__float2bfloat16_rn(o[j]));
                lv.x = pack_bf16_hi(lo[0], lo[1]); lv.y = pack_bf16_hi(lo[2], lo[3]);
                lv.z = pack_bf16_hi(lo[4], lo[5]); lv.w = pack_bf16_hi(lo[6], lo[7]);
                *(uint4*)(g_xhi + (size_t)n * D + tx * 8) = hv;
                *(uint4*)(g_xlo + (size_t)n * D + tx * 8) = lv;
                float* sbase = xsum + (size_t)bat[r] * D + tx * 8;
                red_add_v4(sbase,     o[0], o[1], o[2], o[3]);
                red_add_v4(sbase + 4, o[4], o[5], o[6], o[7]);
            }
        }
    }
}

// ===========================================================================
// Global MLP (unchanged)
// ===========================================================================
__global__ __launch_bounds__(256, 1)
void global_mlp_kernel(const float* __restrict__ u,
                       const float* __restrict__ xsum,
                       const float* __restrict__ bcnt,
                       const float* __restrict__ w1, const float* __restrict__ b1,
                       const float* __restrict__ w2, const float* __restrict__ b2,
                       float* __restrict__ uout)
{
    extern __shared__ float sm[];
    float* G  = sm;              // [64][256]
    float* Hh = G + 64 * 256;    // [64][EPAD]

    const int tid = threadIdx.x;
    const int tx  = tid & 15;
    const int ty  = tid >> 4;

    for (int idx = tid; idx < 64 * 128; idx += 256) {
        int b = idx >> 7, c = idx & 127;
        G[b * 256 + c]       = u[idx];
        G[b * 256 + 128 + c] = xsum[idx] / fmaxf(bcnt[b], 1.0f);
    }
    __syncthreads();

    float acc[4][8];
#pragma unroll
    for (int i = 0; i < 4; ++i)
#pragma unroll
        for (int j = 0; j < 8; ++j) acc[i][j] = 0.f;

#pragma unroll 4
    for (int k = 0; k < 256; ++k) {
        float ra[4];
#pragma unroll
        for (int i = 0; i < 4; ++i) ra[i] = G[(ty * 4 + i) * 256 + k];
        float4 rb0 = __ldg((const float4*)&w1[k * 128 + tx * 8]);
        float4 rb1 = __ldg((const float4*)&w1[k * 128 + tx * 8 + 4]);
        float rb[8] = {rb0.x, rb0.y, rb0.z, rb0.w, rb1.x, rb1.y, rb1.z, rb1.w};
#pragma unroll
        for (int i = 0; i < 4; ++i)
#pragma unroll
            for (int j = 0; j < 8; ++j) acc[i][j] = fmaf(ra[i], rb[j], acc[i][j]);
    }

    {
        float bv[8];
#pragma unroll
        for (int j = 0; j < 8; ++j) bv[j] = b1[tx * 8 + j];
#pragma unroll
        for (int i = 0; i < 4; ++i) {
#pragma unroll
            for (int j = 0; j < 8; ++j) acc[i][j] = fmaxf(acc[i][j] + bv[j], 0.f);
            *(float4*)&Hh[(ty * 4 + i) * EPAD + tx * 8]     = make_float4(acc[i][0], acc[i][1], acc[i][2], acc[i][3]);
            *(float4*)&Hh[(ty * 4 + i) * EPAD + tx * 8 + 4] = make_float4(acc[i][4], acc[i][5], acc[i][6], acc[i][7]);
        }
    }
    __syncthreads();

#pragma unroll
    for (int i = 0; i < 4; ++i)
#pragma unroll
        for (int j = 0; j < 8; ++j) acc[i][j] = 0.f;

#pragma unroll 4
    for (int k = 0; k < 128; ++k) {
        float ra[4];
#pragma unroll
        for (int i = 0; i < 4; ++i) ra[i] = Hh[(ty * 4 + i) * EPAD + k];
        float4 rb0 = __ldg((const float4*)&w2[k * 128 + tx * 8]);
        float4 rb1 = __ldg((const float4*)&w2[k * 128 + tx * 8 + 4]);
        float rb[8] = {rb0.x, rb0.y, rb0.z, rb0.w, rb1.x, rb1.y, rb1.z, rb1.w};
#pragma unroll
        for (int i = 0; i < 4; ++i)
#pragma unroll
            for (int j = 0; j < 8; ++j) acc[i][j] = fmaf(ra[i], rb[j], acc[i][j]);
    }

    {
        float bv[8];
#pragma unroll
        for (int j = 0; j < 8; ++j) bv[j] = b2[tx * 8 + j];
#pragma unroll
        for (int i = 0; i < 4; ++i) {
            int b = ty * 4 + i;
            *(float4*)&uout[b * D + tx * 8]     = make_float4(acc[i][0] + bv[0], acc[i][1] + bv[1],
                                                              acc[i][2] + bv[2], acc[i][3] + bv[3]);
            *(float4*)&uout[b * D + tx * 8 + 4] = make_float4(acc[i][4] + bv[4], acc[i][5] + bv[5],
                                                              acc[i][6] + bv[6], acc[i][7] + bv[7]);
        }
    }
}

// ===========================================================================
// Host side
// ===========================================================================
static const int NODE_SMEM = (128 * HPAD + 32 * 128 + 128 * EPAD + 128) * 4 + 128 * 4;
static const int GLOB_SMEM = (64 * 256 + 64 * EPAD) * 4;

extern "C" void kernel_launch(void* const* d_in, const int* in_sizes, int n_in,
                              void* d_out, int out_size) {
    const float* x0    = (const float*)d_in[0];
    const int*   ei    = (const int*)d_in[1];      // int32 (JAX x64 disabled)
    const float* u0    = (const float*)d_in[2];
    const int*   batch = (const int*)d_in[3];      // int32
    const float* n1w1 = (const float*)d_in[4];
    const float* n1b1 = (const float*)d_in[5];
    const float* n1w2 = (const float*)d_in[6];
    const float* n1b2 = (const float*)d_in[7];
    const float* n2w1 = (const float*)d_in[8];
    const float* n2b1 = (const float*)d_in[9];
    const float* n2w2 = (const float*)d_in[10];
    const float* n2b2 = (const float*)d_in[11];
    const float* gw1  = (const float*)d_in[12];
    const float* gb1  = (const float*)d_in[13];
    const float* gw2  = (const float*)d_in[14];
    const float* gb2  = (const float*)d_in[15];
    float* out = (float*)d_out;

    float *px, *pu, *pagg, *pcnt, *pxsum, *pbcnt;
    unsigned char* pwt;
    cudaGetSymbolAddress((void**)&px,    g_x);
    cudaGetSymbolAddress((void**)&pu,    g_u);
    cudaGetSymbolAddress((void**)&pagg,  g_agg);
    cudaGetSymbolAddress((void**)&pcnt,  g_cnt);
    cudaGetSymbolAddress((void**)&pxsum, g_xsum);
    cudaGetSymbolAddress((void**)&pbcnt, g_bcnt);
    cudaGetSymbolAddress((void**)&pwt,   g_wt);
    float* xbuf[2] = {px, px + (size_t)N_NODES * D};
    float* ubuf[2] = {pu, pu + (size_t)NB * D};

    cudaFuncSetAttribute(edge_mlp_mma_kernel, cudaFuncAttributeMaxDynamicSharedMemorySize, EDGE_SMEM);
    cudaFuncSetAttribute(node_mlp_kernel,     cudaFuncAttributeMaxDynamicSharedMemorySize, NODE_SMEM);
    cudaFuncSetAttribute(global_mlp_kernel,   cudaFuncAttributeMaxDynamicSharedMemorySize, GLOB_SMEM);

    // one-time per launch: counts + weight tiles + layer-0 x split
    cudaMemsetAsync(pcnt,  0, N_NODES * sizeof(float));
    cudaMemsetAsync(pbcnt, 0, NB * sizeof(float));
    count_edges_kernel<<<(N_EDGES + 255) / 256, 256>>>(ei, pcnt);
    count_batch_kernel<<<(N_NODES + 255) / 256, 256>>>(batch, pbcnt);
    prep_weights_kernel<<<2 * NLAYERS, 256>>>(n1w1, n1w2);
    split_x_kernel<<<(N_NODES * (D / 2) + 255) / 256, 256>>>(x0);

    const float* xc = x0;
    const float* uc = u0;
    for (int l = 0; l < NLAYERS; ++l) {
        cudaMemsetAsync(pagg,  0, (size_t)N_NODES * D * sizeof(float));
        cudaMemsetAsync(pxsum, 0, (size_t)NB * D * sizeof(float));

        const unsigned char* w1hi = pwt + (size_t)(l * 4 + 0) * WTILE_BYTES;
        const unsigned char* w1lo = pwt + (size_t)(l * 4 + 1) * WTILE_BYTES;
        const unsigned char* w2hi = pwt + (size_t)(l * 4 + 2) * WTILE_BYTES;
        const unsigned char* w2lo = pwt + (size_t)(l * 4 + 3) * WTILE_BYTES;

        edge_mlp_mma_kernel<<<EDGE_GRID, ETHREADS, EDGE_SMEM>>>(
            ei, w1hi, w1lo, w2hi, w2lo,
            n1b1 + (size_t)l * D, n1b2 + (size_t)l * D, pagg);

        float* xn = (l == NLAYERS - 1) ? out : xbuf[l & 1];
        node_mlp_kernel<<<(N_NODES + 127) / 128, 256, NODE_SMEM>>>(
            xc, pagg, pcnt, uc, batch,
            n2w1 + (size_t)l * 384 * D, n2b1 + (size_t)l * D,
            n2w2 + (size_t)l * D * D,   n2b2 + (size_t)l * D,
            xn, pxsum);

        float* un = (l == NLAYERS - 1) ? out + (size_t)N_NODES * D : ubuf[l & 1];
        global_mlp_kernel<<<1, 256, GLOB_SMEM>>>(
            uc, pxsum, pbcnt,
            gw1 + (size_t)l * 256 * D, gb1 + (size_t)l * D,
            gw2 + (size_t)l * D * D,   gb2 + (size_t)l * D,
            un);

        xc = xn;
        uc = un;
    }
}

// round 14
// speedup vs baseline: 1.3637x; 1.2985x over previous
#include <cuda_runtime.h>
#include <cuda_bf16.h>
#include <cstdint>

#define N_NODES 50000
#define N_EDGES 600000
#define NB      64
#define D       128      // F == H == U
#define NLAYERS 4

#define EPAD 132   // padded row stride for 128-wide smem tiles (global mlp)

#define LDA 136                      // bf16 row stride for W/edge-A tiles (272B)
#define WTILE_BYTES (128 * LDA * 2)  // 34816 bytes per 128x128 bf16 tile
#define ATILE_BYTES (64 * LDA * 2)   // 17408 bytes per 64x128 bf16 tile
#define NT64 (N_EDGES / 64)          // 9375 edge tiles, exact
#define NT_NODE ((N_NODES + 127) / 128)  // 391 node tiles
#define LDN_B 528                    // node A row stride bytes (264 bf16)

// ===========================================================================
// Scratch (no allocations allowed -> __device__ globals)
// ===========================================================================
__device__ float g_x[2][N_NODES * D];
__device__ float g_u[2][NB * D];
__device__ float g_agg[N_NODES * D];
__device__ float g_cnt[N_NODES];
__device__ float g_xsum[NB * D];
__device__ float g_bcnt[NB];
__device__ float g_uprime[NB * D];
// x pre-split into bf16 hi/lo, DOUBLE BUFFERED (node kernel reads one, writes other)
__device__ __align__(16) __nv_bfloat16 g_xhi[2][N_NODES * D];
__device__ __align__(16) __nv_bfloat16 g_xlo[2][N_NODES * D];
// transposed/split bf16 weight tiles [n][k]:
//  tiles 0..15 : edge  (layer, w1/w2, hi/lo)
//  tiles 16..39: node  (layer, {W1a,W1b,W2}, hi/lo)
__device__ __align__(16) unsigned char g_wt[40 * WTILE_BYTES];

__device__ __forceinline__ void red_add_v4(float* addr, float a, float b, float c, float d) {
    asm volatile("red.global.add.v4.f32 [%0], {%1,%2,%3,%4};"
                 :: "l"(addr), "f"(a), "f"(b), "f"(c), "f"(d) : "memory");
}
__device__ __forceinline__ void red_add_v2(float* addr, float a, float b) {
    asm volatile("red.global.add.v2.f32 [%0], {%1,%2};"
                 :: "l"(addr), "f"(a), "f"(b) : "memory");
}

__device__ __forceinline__ uint32_t smem_u32(const void* p) {
    uint32_t a;
    asm("{ .reg .u64 t; cvta.to.shared.u64 t, %1; cvt.u32.u64 %0, t; }" : "=r"(a) : "l"(p));
    return a;
}

__device__ __forceinline__ void ldsm4(uint32_t addr, uint32_t r[4]) {
    asm volatile("ldmatrix.sync.aligned.m8n8.x4.shared.b16 {%0,%1,%2,%3}, [%4];"
                 : "=r"(r[0]), "=r"(r[1]), "=r"(r[2]), "=r"(r[3]) : "r"(addr));
}

__device__ __forceinline__ void mma16816(float d[4], const uint32_t a[4],
                                         uint32_t b0, uint32_t b1) {
    asm volatile(
        "mma.sync.aligned.m16n8k16.row.col.f32.bf16.bf16.f32 "
        "{%0,%1,%2,%3}, {%4,%5,%6,%7}, {%8,%9}, {%0,%1,%2,%3};"
        : "+f"(d[0]), "+f"(d[1]), "+f"(d[2]), "+f"(d[3])
        : "r"(a[0]), "r"(a[1]), "r"(a[2]), "r"(a[3]), "r"(b0), "r"(b1));
}

__device__ __forceinline__ uint32_t pack_bf16_hi(float f0, float f1) {
    return ((uint32_t)__bfloat16_as_ushort(__float2bfloat16_rn(f1)) << 16)
         |  (uint32_t)__bfloat16_as_ushort(__float2bfloat16_rn(f0));
}

#define CP_ASYNC16(dst, src) \
    asm volatile("cp.async.ca.shared.global [%0], [%1], 16;" :: "r"(dst), "l"(src) : "memory")
#define CP_ASYNC4(dst, src) \
    asm volatile("cp.async.ca.shared.global [%0], [%1], 4;"  :: "r"(dst), "l"(src) : "memory")
#define CP_COMMIT() asm volatile("cp.async.commit_group;" ::: "memory")
#define CP_WAIT0()  asm volatile("cp.async.wait_group 0;"  ::: "memory")

// ===========================================================================
// One-time kernels
// ===========================================================================
__global__ void count_edges_kernel(const int* __restrict__ ei, float* __restrict__ cnt) {
    int e = blockIdx.x * 256 + threadIdx.x;
    if (e < N_EDGES) atomicAdd(&cnt[ei[N_EDGES + e]], 1.0f);
}
__global__ void count_batch_kernel(const int* __restrict__ batch, float* __restrict__ bcnt) {
    int n = blockIdx.x * 256 + threadIdx.x;
    if (n < N_NODES) atomicAdd(&bcnt[batch[n]], 1.0f);
}

// Split layer-0 x into bf16 hi/lo buffer 0
__global__ void split_x_kernel(const float* __restrict__ x) {
    int i = blockIdx.x * 256 + threadIdx.x;
    if (i < N_NODES * (D / 2)) {
        float2 v = ((const float2*)x)[i];
        ((uint32_t*)g_xhi[0])[i] = pack_bf16_hi(v.x, v.y);
        float l0 = v.x - __bfloat162float(__float2bfloat16_rn(v.x));
        float l1 = v.y - __bfloat162float(__float2bfloat16_rn(v.y));
        ((uint32_t*)g_xlo[0])[i] = pack_bf16_hi(l0, l1);
    }
}

// Transpose+split weights into bf16 hi/lo tiles [n][k], LDA pad.
// blocks 0..7  : edge   (layer l=b>>1, which=b&1 -> n1w1/n1w2)
// blocks 8..19 : node   (bb=b-8: l=bb/3, j=bb%3 -> W1a, W1b, W2)
__global__ void prep_weights_kernel(const float* __restrict__ n1w1,
                                    const float* __restrict__ n1w2,
                                    const float* __restrict__ n2w1,
                                    const float* __restrict__ n2w2) {
    int b = blockIdx.x;
    const float* w;
    unsigned char *thi, *tlo;
    if (b < 8) {
        int l = b >> 1, which = b & 1;
        w = (which ? n1w2 : n1w1) + (size_t)l * D * D;
        thi = g_wt + (size_t)(b * 2) * WTILE_BYTES;
    } else {
        int bb = b - 8, l = bb / 3, j = bb % 3;
        w = (j < 2) ? n2w1 + (size_t)l * 384 * D + (size_t)j * 128 * D
                    : n2w2 + (size_t)l * D * D;
        thi = g_wt + (size_t)(16 + (l * 3 + j) * 2) * WTILE_BYTES;
    }
    tlo = thi + WTILE_BYTES;
    for (int idx = threadIdx.x; idx < 128 * 32; idx += 256) {
        int n = idx >> 5, kq = (idx & 31) << 2;
        unsigned short hh[4], ll[4];
#pragma unroll
        for (int q = 0; q < 4; ++q) {
            float f = w[(kq + q) * D + n];
            __nv_bfloat16 h = __float2bfloat16_rn(f);
            float r = f - __bfloat162float(h);
            hh[q] = __bfloat16_as_ushort(h);
            ll[q] = __bfloat16_as_ushort(__float2bfloat16_rn(r));
        }
        uint32_t o = (uint32_t)(n * LDA + kq) * 2;
        *(uint2*)(thi + o) = make_uint2(((uint32_t)hh[1] << 16) | hh[0],
                                        ((uint32_t)hh[3] << 16) | hh[2]);
        *(uint2*)(tlo + o) = make_uint2(((uint32_t)ll[1] << 16) | ll[0],
                                        ((uint32_t)ll[3] << 16) | ll[2]);
    }
}

// U' = u @ W1[256:384]  (fp32, 64x128, K=128) -- folds the u-concat out of node GEMM1
__global__ void uprime_kernel(const float* __restrict__ u, const float* __restrict__ w1u) {
    __shared__ float us[128];
    int b = blockIdx.x;
    if (threadIdx.x < 128) us[threadIdx.x] = u[b * D + threadIdx.x];
    __syncthreads();
    int n = threadIdx.x;
    float s = 0.f;
#pragma unroll 4
    for (int k = 0; k < 128; ++k)
        s = fmaf(us[k], __ldg(&w1u[k * D + n]), s);
    g_uprime[b * D + n] = s;
}

// ===========================================================================
// Edge MLP via mma.sync (split-bf16, 3-term), persistent CTAs,
// resident weights, double-buffered 64-row tiles with cp.async prefetch.
// ===========================================================================
#define SM_COLS   0
#define SM_B1     512
#define SM_B2     1024
#define A_OFF     2048
#define W1_HI_OFF (A_OFF + 4 * ATILE_BYTES)
#define W1_LO_OFF (W1_HI_OFF + WTILE_BYTES)
#define W2_HI_OFF (W1_LO_OFF + WTILE_BYTES)
#define W2_LO_OFF (W2_HI_OFF + WTILE_BYTES)
static const int EDGE_SMEM = W2_LO_OFF + WTILE_BYTES;   // 210944
#define ETHREADS 512
#define EDGE_GRID 148

__device__ __forceinline__ void prefetch_tile(int t, int buf, int tid,
                                              uint32_t sbase,
                                              const int* __restrict__ ei,
                                              const __nv_bfloat16* __restrict__ xhi,
                                              const __nv_bfloat16* __restrict__ xlo) {
    if (t >= NT64) return;
    const int e0 = t * 64;
    if (tid < 64)
        CP_ASYNC4(sbase + SM_COLS + buf * 256 + tid * 4,
                  (const char*)(ei + N_EDGES + e0 + tid));
    const int r = tid >> 3;
    const int c = (tid & 7) * 32;
    const int src = ei[e0 + r];
    const char* sh = (const char*)(xhi + (size_t)src * D) + c;
    const char* sl = (const char*)(xlo + (size_t)src * D) + c;
    const uint32_t dh = sbase + A_OFF + buf * 2 * ATILE_BYTES + r * (LDA * 2) + c;
    const uint32_t dl = dh + ATILE_BYTES;
    CP_ASYNC16(dh,      sh);
    CP_ASYNC16(dh + 16, sh + 16);
    CP_ASYNC16(dl,      sl);
    CP_ASYNC16(dl + 16, sl + 16);
}

// split GEMM over K=128 on 64-row A (stride 272B): warp tile 32x16
__device__ __forceinline__ void gemm_split64(uint32_t aHi, uint32_t aLo,
                                             uint32_t wHi, uint32_t wLo,
                                             int mrow, int ncol, int lane,
                                             float d[2][2][4]) {
    const int a_row  = lane & 15;
    const int a_koff = (lane >> 4) << 3;
    const int b_row  = ncol + ((lane >> 4) << 3) + (lane & 7);
    const int b_koff = ((lane >> 3) & 1) << 3;
#pragma unroll
    for (int ks = 0; ks < 8; ++ks) {
        const int kb = ks * 16;
        uint32_t ah[2][4], al[2][4], bh[4], bl[4];
#pragma unroll
        for (int mt = 0; mt < 2; ++mt) {
            uint32_t off = (uint32_t)(((mrow + mt * 16 + a_row) * LDA + kb + a_koff) * 2);
            ldsm4(aHi + off, ah[mt]);
            ldsm4(aLo + off, al[mt]);
        }
        {
            uint32_t off = (uint32_t)((b_row * LDA + kb + b_koff) * 2);
            ldsm4(wHi + off, bh);
            ldsm4(wLo + off, bl);
        }
#pragma unroll
        for (int nt = 0; nt < 2; ++nt)
#pragma unroll
            for (int mt = 0; mt < 2; ++mt) {
                mma16816(d[mt][nt], ah[mt], bh[2 * nt], bh[2 * nt + 1]);
                mma16816(d[mt][nt], ah[mt], bl[2 * nt], bl[2 * nt + 1]);
                mma16816(d[mt][nt], al[mt], bh[2 * nt], bh[2 * nt + 1]);
            }
    }
}

__global__ __launch_bounds__(ETHREADS, 1)
void edge_mlp_mma_kernel(const int* __restrict__ ei,
                         const __nv_bfloat16* __restrict__ xhi,
                         const __nv_bfloat16* __restrict__ xlo,
                         const unsigned char* __restrict__ w1hi, const unsigned char* __restrict__ w1lo,
                         const unsigned char* __restrict__ w2hi, const unsigned char* __restrict__ w2lo,
                         const float* __restrict__ b1, const float* __restrict__ b2,
                         float* __restrict__ agg)
{
    extern __shared__ char smc[];
    float* b1s = (float*)(smc + SM_B1);
    float* b2s = (float*)(smc + SM_B2);

    const int tid  = threadIdx.x;
    const int warp = tid >> 5;
    const int lane = tid & 31;

    const uint32_t sbase = smem_u32(smc);
    const uint32_t w1Hi = sbase + W1_HI_OFF, w1Lo = sbase + W1_LO_OFF;
    const uint32_t w2Hi = sbase + W2_HI_OFF, w2Lo = sbase + W2_LO_OFF;

    {
        uint4* d1h = (uint4*)(smc + W1_HI_OFF);
        uint4* d1l = (uint4*)(smc + W1_LO_OFF);
        uint4* d2h = (uint4*)(smc + W2_HI_OFF);
        uint4* d2l = (uint4*)(smc + W2_LO_OFF);
        const uint4* s1h = (const uint4*)w1hi;
        const uint4* s1l = (const uint4*)w1lo;
        const uint4* s2h = (const uint4*)w2hi;
        const uint4* s2l = (const uint4*)w2lo;
        for (int i = tid; i < WTILE_BYTES / 16; i += ETHREADS) {
            d1h[i] = s1h[i]; d1l[i] = s1l[i];
            d2h[i] = s2h[i]; d2l[i] = s2l[i];
        }
        if (tid < 128) { b1s[tid] = b1[tid]; b2s[tid] = b2[tid]; }
    }

    const int mrow = (warp >> 3) * 32;
    const int ncol = (warp & 7) * 16;
    const int crow = lane >> 2;
    const int ccol = (lane & 3) * 2;

    int t = blockIdx.x;
    int buf = 0;
    prefetch_tile(t, 0, tid, sbase, ei, xhi, xlo);
    CP_COMMIT();

    for (; t < NT64; t += EDGE_GRID, buf ^= 1) {
        CP_WAIT0();
        __syncthreads();

        prefetch_tile(t + EDGE_GRID, buf ^ 1, tid, sbase, ei, xhi, xlo);
        CP_COMMIT();

        const uint32_t aHi = sbase + A_OFF + buf * 2 * ATILE_BYTES;
        const uint32_t aLo = aHi + ATILE_BYTES;
        const int* colSb = (const int*)(smc + SM_COLS + buf * 256);

        float d[2][2][4];
#pragma unroll
        for (int mt = 0; mt < 2; ++mt)
#pragma unroll
            for (int nt = 0; nt < 2; ++nt)
#pragma unroll
                for (int q = 0; q < 4; ++q) d[mt][nt][q] = 0.f;

        gemm_split64(aHi, aLo, w1Hi, w1Lo, mrow, ncol, lane, d);
        __syncthreads();

#pragma unroll
        for (int mt = 0; mt < 2; ++mt) {
#pragma unroll
            for (int nt = 0; nt < 2; ++nt) {
                const int row = mrow + mt * 16 + crow;
                const int col = ncol + nt * 8 + ccol;
                float f0 = fmaxf(d[mt][nt][0] + b1s[col],     0.f);
                float f1 = fmaxf(d[mt][nt][1] + b1s[col + 1], 0.f);
                float f2 = fmaxf(d[mt][nt][2] + b1s[col],     0.f);
                float f3 = fmaxf(d[mt][nt][3] + b1s[col + 1], 0.f);
                uint32_t o0 = (uint32_t)(row * LDA + col) * 2;
                uint32_t o1 = (uint32_t)((row + 8) * LDA + col) * 2;
                char* abase = smc + A_OFF + buf * 2 * ATILE_BYTES;
                *(uint32_t*)(abase + o0) = pack_bf16_hi(f0, f1);
                *(uint32_t*)(abase + o1) = pack_bf16_hi(f2, f3);
                float r0 = f0 - __bfloat162float(__float2bfloat16_rn(f0));
                float r1 = f1 - __bfloat162float(__float2bfloat16_rn(f1));
                float r2 = f2 - __bfloat162float(__float2bfloat16_rn(f2));
                float r3 = f3 - __bfloat162float(__float2bfloat16_rn(f3));
                *(uint32_t*)(abase + ATILE_BYTES + o0) = pack_bf16_hi(r0, r1);
                *(uint32_t*)(abase + ATILE_BYTES + o1) = pack_bf16_hi(r2, r3);
            }
        }
        __syncthreads();

#pragma unroll
        for (int mt = 0; mt < 2; ++mt)
#pragma unroll
            for (int nt = 0; nt < 2; ++nt)
#pragma unroll
                for (int q = 0; q < 4; ++q) d[mt][nt][q] = 0.f;

        gemm_split64(aHi, aLo, w2Hi, w2Lo, mrow, ncol, lane, d);

#pragma unroll
        for (int mt = 0; mt < 2; ++mt) {
            const int row0 = mrow + mt * 16 + crow;
            const int c0 = colSb[row0];
            const int c1 = colSb[row0 + 8];
#pragma unroll
            for (int nt = 0; nt < 2; ++nt) {
                const int col = ncol + nt * 8 + ccol;
                red_add_v2(agg + (size_t)c0 * D + col,
                           d[mt][nt][0] + b2s[col], d[mt][nt][1] + b2s[col + 1]);
                red_add_v2(agg + (size_t)c1 * D + col,
                           d[mt][nt][2] + b2s[col], d[mt][nt][3] + b2s[col + 1]);
            }
        }
    }
}

// ===========================================================================
// Node MLP via mma.sync (split-bf16, 3-term), K folded to 256 (u -> U' bias).
// 128-node tiles; A in smem (stride 264 bf16); W streamed through one slot.
// ===========================================================================
#define NSM_RCP 0
#define NSM_BAT 512
#define NSM_B1  1024
#define NSM_B2  1536
#define NA_HI   2048
#define NA_LO   (NA_HI + 128 * LDN_B)     // 69632
#define NW_HI   (NA_LO + 128 * LDN_B)     // 137216
#define NW_LO   (NW_HI + WTILE_BYTES)     // 172032
static const int NODE2_SMEM = NW_LO + WTILE_BYTES;   // 206848

// split GEMM over K=128 on 128-row A (stride LDN_B), W stride 272B; warp tile 32x32
__device__ __forceinline__ void gemm_split32n(uint32_t aHi, uint32_t aLo,
                                              uint32_t wHi, uint32_t wLo,
                                              int mrow, int ncol, int lane,
                                              float d[2][4][4]) {
    const int a_row  = lane & 15;
    const int a_koff = (lane >> 4) << 3;
    const int b_nrow = ((lane >> 4) << 3) + (lane & 7);
    const int b_koff = ((lane >> 3) & 1) << 3;
#pragma unroll
    for (int ks = 0; ks < 8; ++ks) {
        const int kb = ks * 16;
        uint32_t ah[2][4], al[2][4], bh[2][4], bl[2][4];
#pragma unroll
        for (int mt = 0; mt < 2; ++mt) {
            uint32_t off = (uint32_t)((mrow + mt * 16 + a_row) * LDN_B + (kb + a_koff) * 2);
            ldsm4(aHi + off, ah[mt]);
            ldsm4(aLo + off, al[mt]);
        }
#pragma unroll
        for (int p = 0; p < 2; ++p) {
            uint32_t off = (uint32_t)(((ncol + p * 16 + b_nrow) * LDA + kb + b_koff) * 2);
            ldsm4(wHi + off, bh[p]);
            ldsm4(wLo + off, bl[p]);
        }
#pragma unroll
        for (int p = 0; p < 2; ++p)
#pragma unroll
            for (int h = 0; h < 2; ++h)
#pragma unroll
                for (int mt = 0; mt < 2; ++mt) {
                    mma16816(d[mt][p * 2 + h], ah[mt], bh[p][2 * h], bh[p][2 * h + 1]);
                    mma16816(d[mt][p * 2 + h], ah[mt], bl[p][2 * h], bl[p][2 * h + 1]);
                    mma16816(d[mt][p * 2 + h], al[mt], bh[p][2 * h], bh[p][2 * h + 1]);
                }
    }
}

__global__ __launch_bounds__(512, 1)
void node_mlp_mma_kernel(const float* __restrict__ agg,
                         const float* __restrict__ cnt,
                         const int* __restrict__ batch,
                         const __nv_bfloat16* __restrict__ xhi_r,
                         const __nv_bfloat16* __restrict__ xlo_r,
                         const unsigned char* __restrict__ wbase,  // 6 tiles: W1a hi/lo, W1b hi/lo, W2 hi/lo
                         const float* __restrict__ b1, const float* __restrict__ b2,
                         const float* __restrict__ uprime,
                         float* __restrict__ xout, float* __restrict__ xsum,
                         __nv_bfloat16* __restrict__ xhi_w,
                         __nv_bfloat16* __restrict__ xlo_w)
{
    extern __shared__ char smc[];
    float* rcp = (float*)(smc + NSM_RCP);
    int*   bat = (int*)(smc + NSM_BAT);
    float* b1s = (float*)(smc + NSM_B1);
    float* b2s = (float*)(smc + NSM_B2);

    const uint32_t sbase = smem_u32(smc);
    const uint32_t aHi = sbase + NA_HI, aLo = sbase + NA_LO;
    const uint32_t wHi = sbase + NW_HI, wLo = sbase + NW_LO;

    const int tid = threadIdx.x, warp = tid >> 5, lane = tid & 31;
    const int n0 = blockIdx.x * 128;

    if (tid < 128) {
        int n = n0 + tid;
        if (n < N_NODES) { rcp[tid] = 1.f / fmaxf(cnt[n], 1.f); bat[tid] = batch[n]; }
        else             { rcp[tid] = 0.f; bat[tid] = 0; }
        b1s[tid] = b1[tid]; b2s[tid] = b2[tid];
    }
    // W1a (hi+lo contiguous in g_wt) -> W slot
    {
        uint4* dw = (uint4*)(smc + NW_HI);
        const uint4* sw = (const uint4*)wbase;
        for (int i = tid; i < (2 * WTILE_BYTES) / 16; i += 512) dw[i] = sw[i];
    }
    __syncthreads();   // rcp ready for A build

    // build A: x part (cols 0..127) from pre-split buffers
    for (int idx = tid; idx < 128 * 16; idx += 512) {
        int r = idx >> 4, q = idx & 15;
        int n = n0 + r;
        uint4 h = make_uint4(0, 0, 0, 0), l = make_uint4(0, 0, 0, 0);
        if (n < N_NODES) {
            h = *(const uint4*)(xhi_r + (size_t)n * D + q * 8);
            l = *(const uint4*)(xlo_r + (size_t)n * D + q * 8);
        }
        *(uint4*)(smc + NA_HI + r * LDN_B + q * 16) = h;
        *(uint4*)(smc + NA_LO + r * LDN_B + q * 16) = l;
    }
    // agg part (cols 128..255): scale + split
    for (int idx = tid; idx < 128 * 64; idx += 512) {
        int r = idx >> 6, c2 = idx & 63;
        int n = n0 + r;
        float2 v = make_float2(0.f, 0.f);
        if (n < N_NODES) v = *(const float2*)(agg + (size_t)n * D + c2 * 2);
        float s = rcp[r];
        v.x *= s; v.y *= s;
        float l0 = v.x - __bfloat162float(__float2bfloat16_rn(v.x));
        float l1 = v.y - __bfloat162float(__float2bfloat16_rn(v.y));
        *(uint32_t*)(smc + NA_HI + r * LDN_B + 256 + c2 * 4) = pack_bf16_hi(v.x, v.y);
        *(uint32_t*)(smc + NA_LO + r * LDN_B + 256 + c2 * 4) = pack_bf16_hi(l0, l1);
    }
    __syncthreads();   // A + W1a ready

    const int mrow = (warp >> 2) * 32;
    const int ncol = (warp & 3) * 32;
    const int crow = lane >> 2, ccol = (lane & 3) * 2;

    float d[2][4][4];
#pragma unroll
    for (int mt = 0; mt < 2; ++mt)
#pragma unroll
        for (int nt = 0; nt < 4; ++nt)
#pragma unroll
            for (int q = 0; q < 4; ++q) d[mt][nt][q] = 0.f;

    // GEMM1a: x part @ W1a
    gemm_split32n(aHi, aLo, wHi, wLo, mrow, ncol, lane, d);
    __syncthreads();
    // W1b -> W slot
    {
        uint4* dw = (uint4*)(smc + NW_HI);
        const uint4* sw = (const uint4*)(wbase + 2 * WTILE_BYTES);
        for (int i = tid; i < (2 * WTILE_BYTES) / 16; i += 512) dw[i] = sw[i];
    }
    __syncthreads();
    // GEMM1b: agg part @ W1b (A cols 128..255 = +256 bytes)
    gemm_split32n(aHi + 256, aLo + 256, wHi, wLo, mrow, ncol, lane, d);

    // Epilogue 1: h = relu(d + b1 + U'[bat]), split, T -> A cols 0..127
#pragma unroll
    for (int mt = 0; mt < 2; ++mt) {
        const int r0 = mrow + mt * 16 + crow, r1 = r0 + 8;
        const int bb0 = bat[r0], bb1 = bat[r1];
#pragma unroll
        for (int nt = 0; nt < 4; ++nt) {
            const int col = ncol + nt * 8 + ccol;
            float2 u0 = *(const float2*)(uprime + (size_t)bb0 * D + col);
            float2 u1 = *(const float2*)(uprime + (size_t)bb1 * D + col);
            float f0 = fmaxf(d[mt][nt][0] + b1s[col]     + u0.x, 0.f);
            float f1 = fmaxf(d[mt][nt][1] + b1s[col + 1] + u0.y, 0.f);
            float f2 = fmaxf(d[mt][nt][2] + b1s[col]     + u1.x, 0.f);
            float f3 = fmaxf(d[mt][nt][3] + b1s[col + 1] + u1.y, 0.f);
            uint32_t o0 = (uint32_t)(r0 * LDN_B + col * 2);
            uint32_t o1 = (uint32_t)(r1 * LDN_B + col * 2);
            *(uint32_t*)(smc + NA_HI + o0) = pack_bf16_hi(f0, f1);
            *(uint32_t*)(smc + NA_HI + o1) = pack_bf16_hi(f2, f3);
            float l0 = f0 - __bfloat162float(__float2bfloat16_rn(f0));
            float l1 = f1 - __bfloat162float(__float2bfloat16_rn(f1));
            float l2 = f2 - __bfloat162float(__float2bfloat16_rn(f2));
            float l3 = f3 - __bfloat162float(__float2bfloat16_rn(f3));
            *(uint32_t*)(smc + NA_LO + o0) = pack_bf16_hi(l0, l1);
            *(uint32_t*)(smc + NA_LO + o1) = pack_bf16_hi(l2, l3);
        }
    }
    __syncthreads();   // all GEMM1b W reads + T writes done
    // W2 -> W slot
    {
        uint4* dw = (uint4*)(smc + NW_HI);
        const uint4* sw = (const uint4*)(wbase + 4 * WTILE_BYTES);
        for (int i = tid; i < (2 * WTILE_BYTES) / 16; i += 512) dw[i] = sw[i];
    }
    __syncthreads();

#pragma unroll
    for (int mt = 0; mt < 2; ++mt)
#pragma unroll
        for (int nt = 0; nt < 4; ++nt)
#pragma unroll
            for (int q = 0; q < 4; ++q) d[mt][nt][q] = 0.f;

    // GEMM2: T @ W2
    gemm_split32n(aHi, aLo, wHi, wLo, mrow, ncol, lane, d);

    // Epilogue 2: o = d + b2; store x', split for next layer, xsum scatter
#pragma unroll
    for (int mt = 0; mt < 2; ++mt) {
        const int r0 = mrow + mt * 16 + crow, r1 = r0 + 8;
        const int nn0 = n0 + r0, nn1 = n0 + r1;
        const int bb0 = bat[r0], bb1 = bat[r1];
#pragma unroll
        for (int nt = 0; nt < 4; ++nt) {
            const int col = ncol + nt * 8 + ccol;
            float o0 = d[mt][nt][0] + b2s[col];
            float o1 = d[mt][nt][1] + b2s[col + 1];
            float o2 = d[mt][nt][2] + b2s[col];
            float o3 = d[mt][nt][3] + b2s[col + 1];
            if (nn0 < N_NODES) {
                *(float2*)(xout + (size_t)nn0 * D + col) = make_float2(o0, o1);
                *(uint32_t*)(xhi_w + (size_t)nn0 * D + col) = pack_bf16_hi(o0, o1);
                float l0 = o0 - __bfloat162float(__float2bfloat16_rn(o0));
                float l1 = o1 - __bfloat162float(__float2bfloat16_rn(o1));
                *(uint32_t*)(xlo_w + (size_t)nn0 * D + col) = pack_bf16_hi(l0, l1);
                red_add_v2(xsum + (size_t)bb0 * D + col, o0, o1);
            }
            if (nn1 < N_NODES) {
                *(float2*)(xout + (size_t)nn1 * D + col) = make_float2(o2, o3);
                *(uint32_t*)(xhi_w + (size_t)nn1 * D + col) = pack_bf16_hi(o2, o3);
                float l2 = o2 - __bfloat162float(__float2bfloat16_rn(o2));
                float l3 = o3 - __bfloat162float(__float2bfloat16_rn(o3));
                *(uint32_t*)(xlo_w + (size_t)nn1 * D + col) = pack_bf16_hi(l2, l3);
                red_add_v2(xsum + (size_t)bb1 * D + col, o2, o3);
            }
        }
    }
}

// ===========================================================================
// Global MLP (unchanged)
// ===========================================================================
__global__ __launch_bounds__(256, 1)
void global_mlp_kernel(const float* __restrict__ u,
                       const float* __restrict__ xsum,
                       const float* __restrict__ bcnt,
                       const float* __restrict__ w1, const float* __restrict__ b1,
                       const float* __restrict__ w2, const float* __restrict__ b2,
                       float* __restrict__ uout)
{
    extern __shared__ float sm[];
    float* G  = sm;              // [64][256]
    float* Hh = G + 64 * 256;    // [64][EPAD]

    const int tid = threadIdx.x;
    const int tx  = tid & 15;
    const int ty  = tid >> 4;

    for (int idx = tid; idx < 64 * 128; idx += 256) {
        int b = idx >> 7, c = idx & 127;
        G[b * 256 + c]       = u[idx];
        G[b * 256 + 128 + c] = xsum[idx] / fmaxf(bcnt[b], 1.0f);
    }
    __syncthreads();

    float acc[4][8];
#pragma unroll
    for (int i = 0; i < 4; ++i)
#pragma unroll
        for (int j = 0; j < 8; ++j) acc[i][j] = 0.f;

#pragma unroll 4
    for (int k = 0; k < 256; ++k) {
        float ra[4];
#pragma unroll
        for (int i = 0; i < 4; ++i) ra[i] = G[(ty * 4 + i) * 256 + k];
        float4 rb0 = __ldg((const float4*)&w1[k * 128 + tx * 8]);
        float4 rb1 = __ldg((const float4*)&w1[k * 128 + tx * 8 + 4]);
        float rb[8] = {rb0.x, rb0.y, rb0.z, rb0.w, rb1.x, rb1.y, rb1.z, rb1.w};
#pragma unroll
        for (int i = 0; i < 4; ++i)
#pragma unroll
            for (int j = 0; j < 8; ++j) acc[i][j] = fmaf(ra[i], rb[j], acc[i][j]);
    }

    {
        float bv[8];
#pragma unroll
        for (int j = 0; j < 8; ++j) bv[j] = b1[tx * 8 + j];
#pragma unroll
        for (int i = 0; i < 4; ++i) {
#pragma unroll
            for (int j = 0; j < 8; ++j) acc[i][j] = fmaxf(acc[i][j] + bv[j], 0.f);
            *(float4*)&Hh[(ty * 4 + i) * EPAD + tx * 8]     = make_float4(acc[i][0], acc[i][1], acc[i][2], acc[i][3]);
            *(float4*)&Hh[(ty * 4 + i) * EPAD + tx * 8 + 4] = make_float4(acc[i][4], acc[i][5], acc[i][6], acc[i][7]);
        }
    }
    __syncthreads();

#pragma unroll
    for (int i = 0; i < 4; ++i)
#pragma unroll
        for (int j = 0; j < 8; ++j) acc[i][j] = 0.f;

#pragma unroll 4
    for (int k = 0; k < 128; ++k) {
        float ra[4];
#pragma unroll
        for (int i = 0; i < 4; ++i) ra[i] = Hh[(ty * 4 + i) * EPAD + k];
        float4 rb0 = __ldg((const float4*)&w2[k * 128 + tx * 8]);
        float4 rb1 = __ldg((const float4*)&w2[k * 128 + tx * 8 + 4]);
        float rb[8] = {rb0.x, rb0.y, rb0.z, rb0.w, rb1.x, rb1.y, rb1.z, rb1.w};
#pragma unroll
        for (int i = 0; i < 4; ++i)
#pragma unroll
            for (int j = 0; j < 8; ++j) acc[i][j] = fmaf(ra[i], rb[j], acc[i][j]);
    }

    {
        float bv[8];
#pragma unroll
        for (int j = 0; j < 8; ++j) bv[j] = b2[tx * 8 + j];
#pragma unroll
        for (int i = 0; i < 4; ++i) {
            int b = ty * 4 + i;
            *(float4*)&uout[b * D + tx * 8]     = make_float4(acc[i][0] + bv[0], acc[i][1] + bv[1],
                                                              acc[i][2] + bv[2], acc[i][3] + bv[3]);
            *(float4*)&uout[b * D + tx * 8 + 4] = make_float4(acc[i][4] + bv[4], acc[i][5] + bv[5],
                                                              acc[i][6] + bv[6], acc[i][7] + bv[7]);
        }
    }
}

// ===========================================================================
// Host side
// ===========================================================================
static const int GLOB_SMEM = (64 * 256 + 64 * EPAD) * 4;

extern "C" void kernel_launch(void* const* d_in, const int* in_sizes, int n_in,
                              void* d_out, int out_size) {
    const float* x0    = (const float*)d_in[0];
    const int*   ei    = (const int*)d_in[1];      // int32 (JAX x64 disabled)
    const float* u0    = (const float*)d_in[2];
    const int*   batch = (const int*)d_in[3];      // int32
    const float* n1w1 = (const float*)d_in[4];
    const float* n1b1 = (const float*)d_in[5];
    const float* n1w2 = (const float*)d_in[6];
    const float* n1b2 = (const float*)d_in[7];
    const float* n2w1 = (const float*)d_in[8];
    const float* n2b1 = (const float*)d_in[9];
    const float* n2w2 = (const float*)d_in[10];
    const float* n2b2 = (const float*)d_in[11];
    const float* gw1  = (const float*)d_in[12];
    const float* gb1  = (const float*)d_in[13];
    const float* gw2  = (const float*)d_in[14];
    const float* gb2  = (const float*)d_in[15];
    float* out = (float*)d_out;

    float *px, *pu, *pagg, *pcnt, *pxsum, *pbcnt, *pup;
    unsigned char* pwt;
    __nv_bfloat16 *pxhi, *pxlo;
    cudaGetSymbolAddress((void**)&px,    g_x);
    cudaGetSymbolAddress((void**)&pu,    g_u);
    cudaGetSymbolAddress((void**)&pagg,  g_agg);
    cudaGetSymbolAddress((void**)&pcnt,  g_cnt);
    cudaGetSymbolAddress((void**)&pxsum, g_xsum);
    cudaGetSymbolAddress((void**)&pbcnt, g_bcnt);
    cudaGetSymbolAddress((void**)&pup,   g_uprime);
    cudaGetSymbolAddress((void**)&pwt,   g_wt);
    cudaGetSymbolAddress((void**)&pxhi,  g_xhi);
    cudaGetSymbolAddress((void**)&pxlo,  g_xlo);
    float* xbuf[2] = {px, px + (size_t)N_NODES * D};
    float* ubuf[2] = {pu, pu + (size_t)NB * D};
    __nv_bfloat16* xhib[2] = {pxhi, pxhi + (size_t)N_NODES * D};
    __nv_bfloat16* xlob[2] = {pxlo, pxlo + (size_t)N_NODES * D};

    cudaFuncSetAttribute(edge_mlp_mma_kernel, cudaFuncAttributeMaxDynamicSharedMemorySize, EDGE_SMEM);
    cudaFuncSetAttribute(node_mlp_mma_kernel, cudaFuncAttributeMaxDynamicSharedMemorySize, NODE2_SMEM);
    cudaFuncSetAttribute(global_mlp_kernel,   cudaFuncAttributeMaxDynamicSharedMemorySize, GLOB_SMEM);

    // one-time: counts + weight tiles + layer-0 x split
    cudaMemsetAsync(pcnt,  0, N_NODES * sizeof(float));
    cudaMemsetAsync(pbcnt, 0, NB * sizeof(float));
    count_edges_kernel<<<(N_EDGES + 255) / 256, 256>>>(ei, pcnt);
    count_batch_kernel<<<(N_NODES + 255) / 256, 256>>>(batch, pbcnt);
    prep_weights_kernel<<<20, 256>>>(n1w1, n1w2, n2w1, n2w2);
    split_x_kernel<<<(N_NODES * (D / 2) + 255) / 256, 256>>>(x0);

    const float* uc = u0;
    for (int l = 0; l < NLAYERS; ++l) {
        const int rd = l & 1, wr = rd ^ 1;
        cudaMemsetAsync(pagg,  0, (size_t)N_NODES * D * sizeof(float));
        cudaMemsetAsync(pxsum, 0, (size_t)NB * D * sizeof(float));

        const unsigned char* ew1hi = pwt + (size_t)(l * 4 + 0) * WTILE_BYTES;
        const unsigned char* ew1lo = pwt + (size_t)(l * 4 + 1) * WTILE_BYTES;
        const unsigned char* ew2hi = pwt + (size_t)(l * 4 + 2) * WTILE_BYTES;
        const unsigned char* ew2lo = pwt + (size_t)(l * 4 + 3) * WTILE_BYTES;
        const unsigned char* nwb   = pwt + (size_t)(16 + l * 6) * WTILE_BYTES;

        edge_mlp_mma_kernel<<<EDGE_GRID, ETHREADS, EDGE_SMEM>>>(
            ei, xhib[rd], xlob[rd], ew1hi, ew1lo, ew2hi, ew2lo,
            n1b1 + (size_t)l * D, n1b2 + (size_t)l * D, pagg);

        uprime_kernel<<<NB, 128>>>(uc, n2w1 + (size_t)l * 384 * D + 256 * D);

        float* xn = (l == NLAYERS - 1) ? out : xbuf[l & 1];
        node_mlp_mma_kernel<<<NT_NODE, 512, NODE2_SMEM>>>(
            pagg, pcnt, batch, xhib[rd], xlob[rd], nwb,
            n2b1 + (size_t)l * D, n2b2 + (size_t)l * D, pup,
            xn, pxsum, xhib[wr], xlob[wr]);

        float* un = (l == NLAYERS - 1) ? out + (size_t)N_NODES * D : ubuf[l & 1];
        global_mlp_kernel<<<1, 256, GLOB_SMEM>>>(
            uc, pxsum, pbcnt,
            gw1 + (size_t)l * 256 * D, gb1 + (size_t)l * D,
            gw2 + (size_t)l * D * D,   gb2 + (size_t)l * D,
            un);

        uc = un;
    }
}

// round 15
// speedup vs baseline: 1.3990x; 1.0259x over previous
#include <cuda_runtime.h>
#include <cuda_bf16.h>
#include <cstdint>

#define N_NODES 50000
#define N_EDGES 600000
#define NB      64
#define D       128      // F == H == U
#define NLAYERS 4

#define EPAD 132   // padded row stride for 128-wide smem tiles (global mlp)

#define LDA 136                      // bf16 row stride for W/edge-A tiles (272B)
#define WTILE_BYTES (128 * LDA * 2)  // 34816 bytes per 128x128 bf16 tile
#define ATILE_BYTES (64 * LDA * 2)   // 17408 bytes per 64x128 bf16 tile
#define NT64 (N_EDGES / 64)          // 9375 edge tiles, exact
#define NT_NODE ((N_NODES + 127) / 128)  // 391 node tiles
#define LDN_B 528                    // node A row stride bytes (264 bf16)

// ===========================================================================
// Scratch (no allocations allowed -> __device__ globals)
// ===========================================================================
__device__ float g_x[2][N_NODES * D];
__device__ float g_u[2][NB * D];
__device__ float g_agg[N_NODES * D];
__device__ float g_cnt[N_NODES];
__device__ float g_xsum[NB * D];
__device__ float g_bcnt[NB];
__device__ float g_uprime[NB * D];
// x pre-split into bf16 hi/lo, DOUBLE BUFFERED (node kernel reads one, writes other)
__device__ __align__(16) __nv_bfloat16 g_xhi[2][N_NODES * D];
__device__ __align__(16) __nv_bfloat16 g_xlo[2][N_NODES * D];
// transposed/split bf16 weight tiles [n][k]:
//  tiles 0..15 : edge  (layer, w1/w2, hi/lo)
//  tiles 16..39: node  (layer, {W1a,W1b,W2}, hi/lo)
__device__ __align__(16) unsigned char g_wt[40 * WTILE_BYTES];

__device__ __forceinline__ void red_add_v4(float* addr, float a, float b, float c, float d) {
    asm volatile("red.global.add.v4.f32 [%0], {%1,%2,%3,%4};"
                 :: "l"(addr), "f"(a), "f"(b), "f"(c), "f"(d) : "memory");
}
__device__ __forceinline__ void red_add_v2(float* addr, float a, float b) {
    asm volatile("red.global.add.v2.f32 [%0], {%1,%2};"
                 :: "l"(addr), "f"(a), "f"(b) : "memory");
}

__device__ __forceinline__ uint32_t smem_u32(const void* p) {
    uint32_t a;
    asm("{ .reg .u64 t; cvta.to.shared.u64 t, %1; cvt.u32.u64 %0, t; }" : "=r"(a) : "l"(p));
    return a;
}

__device__ __forceinline__ void ldsm4(uint32_t addr, uint32_t r[4]) {
    asm volatile("ldmatrix.sync.aligned.m8n8.x4.shared.b16 {%0,%1,%2,%3}, [%4];"
                 : "=r"(r[0]), "=r"(r[1]), "=r"(r[2]), "=r"(r[3]) : "r"(addr));
}

__device__ __forceinline__ void mma16816(float d[4], const uint32_t a[4],
                                         uint32_t b0, uint32_t b1) {
    asm volatile(
        "mma.sync.aligned.m16n8k16.row.col.f32.bf16.bf16.f32 "
        "{%0,%1,%2,%3}, {%4,%5,%6,%7}, {%8,%9}, {%0,%1,%2,%3};"
        : "+f"(d[0]), "+f"(d[1]), "+f"(d[2]), "+f"(d[3])
        : "r"(a[0]), "r"(a[1]), "r"(a[2]), "r"(a[3]), "r"(b0), "r"(b1));
}

__device__ __forceinline__ uint32_t pack_bf16_hi(float f0, float f1) {
    return ((uint32_t)__bfloat16_as_ushort(__float2bfloat16_rn(f1)) << 16)
         |  (uint32_t)__bfloat16_as_ushort(__float2bfloat16_rn(f0));
}

#define CP_ASYNC16(dst, src) \
    asm volatile("cp.async.ca.shared.global [%0], [%1], 16;" :: "r"(dst), "l"(src) : "memory")
#define CP_ASYNC4(dst, src) \
    asm volatile("cp.async.ca.shared.global [%0], [%1], 4;"  :: "r"(dst), "l"(src) : "memory")
#define CP_COMMIT() asm volatile("cp.async.commit_group;" ::: "memory")
#define CP_WAIT0()  asm volatile("cp.async.wait_group 0;"  ::: "memory")
// group barrier: named barrier (g+1), 256 threads
#define GBAR(g) asm volatile("bar.sync %0, 256;" :: "r"((g) + 1) : "memory")

// ===========================================================================
// One-time kernels
// ===========================================================================
__global__ void count_edges_kernel(const int* __restrict__ ei, float* __restrict__ cnt) {
    int e = blockIdx.x * 256 + threadIdx.x;
    if (e < N_EDGES) atomicAdd(&cnt[ei[N_EDGES + e]], 1.0f);
}
__global__ void count_batch_kernel(const int* __restrict__ batch, float* __restrict__ bcnt) {
    int n = blockIdx.x * 256 + threadIdx.x;
    if (n < N_NODES) atomicAdd(&bcnt[batch[n]], 1.0f);
}

// Split layer-0 x into bf16 hi/lo buffer 0
__global__ void split_x_kernel(const float* __restrict__ x) {
    int i = blockIdx.x * 256 + threadIdx.x;
    if (i < N_NODES * (D / 2)) {
        float2 v = ((const float2*)x)[i];
        ((uint32_t*)g_xhi[0])[i] = pack_bf16_hi(v.x, v.y);
        float l0 = v.x - __bfloat162float(__float2bfloat16_rn(v.x));
        float l1 = v.y - __bfloat162float(__float2bfloat16_rn(v.y));
        ((uint32_t*)g_xlo[0])[i] = pack_bf16_hi(l0, l1);
    }
}

// Transpose+split weights into bf16 hi/lo tiles [n][k], LDA pad.
__global__ void prep_weights_kernel(const float* __restrict__ n1w1,
                                    const float* __restrict__ n1w2,
                                    const float* __restrict__ n2w1,
                                    const float* __restrict__ n2w2) {
    int b = blockIdx.x;
    const float* w;
    unsigned char *thi, *tlo;
    if (b < 8) {
        int l = b >> 1, which = b & 1;
        w = (which ? n1w2 : n1w1) + (size_t)l * D * D;
        thi = g_wt + (size_t)(b * 2) * WTILE_BYTES;
    } else {
        int bb = b - 8, l = bb / 3, j = bb % 3;
        w = (j < 2) ? n2w1 + (size_t)l * 384 * D + (size_t)j * 128 * D
                    : n2w2 + (size_t)l * D * D;
        thi = g_wt + (size_t)(16 + (l * 3 + j) * 2) * WTILE_BYTES;
    }
    tlo = thi + WTILE_BYTES;
    for (int idx = threadIdx.x; idx < 128 * 32; idx += 256) {
        int n = idx >> 5, kq = (idx & 31) << 2;
        unsigned short hh[4], ll[4];
#pragma unroll
        for (int q = 0; q < 4; ++q) {
            float f = w[(kq + q) * D + n];
            __nv_bfloat16 h = __float2bfloat16_rn(f);
            float r = f - __bfloat162float(h);
            hh[q] = __bfloat16_as_ushort(h);
            ll[q] = __bfloat16_as_ushort(__float2bfloat16_rn(r));
        }
        uint32_t o = (uint32_t)(n * LDA + kq) * 2;
        *(uint2*)(thi + o) = make_uint2(((uint32_t)hh[1] << 16) | hh[0],
                                        ((uint32_t)hh[3] << 16) | hh[2]);
        *(uint2*)(tlo + o) = make_uint2(((uint32_t)ll[1] << 16) | ll[0],
                                        ((uint32_t)ll[3] << 16) | ll[2]);
    }
}

// U' = u @ W1[256:384]  (fp32, 64x128, K=128)
__global__ void uprime_kernel(const float* __restrict__ u, const float* __restrict__ w1u) {
    __shared__ float us[128];
    int b = blockIdx.x;
    if (threadIdx.x < 128) us[threadIdx.x] = u[b * D + threadIdx.x];
    __syncthreads();
    int n = threadIdx.x;
    float s = 0.f;
#pragma unroll 4
    for (int k = 0; k < 128; ++k)
        s = fmaf(us[k], __ldg(&w1u[k * D + n]), s);
    g_uprime[b * D + n] = s;
}

// ===========================================================================
// Edge MLP via mma.sync (split-bf16, 3-term), persistent CTAs, resident
// weights. TWO independent 8-warp groups per CTA, each with its own 64-row
// tile stream and A buffer; named barriers per group. Warp tile 32x32
// (2Mx4N per group) -> 33% less LDSM traffic than 32x16; cross-group
// scheduling hides each group's gather latency.
// ===========================================================================
#define SM_COLS   0                               // int[2][64]
#define SM_B1     512
#define SM_B2     1024
#define A_OFF     2048                            // [group][hi,lo] 4 x ATILE
#define W1_HI_OFF (A_OFF + 4 * ATILE_BYTES)
#define W1_LO_OFF (W1_HI_OFF + WTILE_BYTES)
#define W2_HI_OFF (W1_LO_OFF + WTILE_BYTES)
#define W2_LO_OFF (W2_HI_OFF + WTILE_BYTES)
static const int EDGE_SMEM = W2_LO_OFF + WTILE_BYTES;   // 210944
#define ETHREADS 512
#define EDGE_GRID 148

// split GEMM over K=128 on 64-row A (stride 272B): warp tile 32x32
__device__ __forceinline__ void gemm_split32e(uint32_t aHi, uint32_t aLo,
                                              uint32_t wHi, uint32_t wLo,
                                              int mrow, int ncol, int lane,
                                              float d[2][4][4]) {
    const int a_row  = lane & 15;
    const int a_koff = (lane >> 4) << 3;
    const int b_nrow = ((lane >> 4) << 3) + (lane & 7);
    const int b_koff = ((lane >> 3) & 1) << 3;
#pragma unroll
    for (int ks = 0; ks < 8; ++ks) {
        const int kb = ks * 16;
        uint32_t ah[2][4], al[2][4], bh[2][4], bl[2][4];
#pragma unroll
        for (int mt = 0; mt < 2; ++mt) {
            uint32_t off = (uint32_t)(((mrow + mt * 16 + a_row) * LDA + kb + a_koff) * 2);
            ldsm4(aHi + off, ah[mt]);
            ldsm4(aLo + off, al[mt]);
        }
#pragma unroll
        for (int p = 0; p < 2; ++p) {
            uint32_t off = (uint32_t)(((ncol + p * 16 + b_nrow) * LDA + kb + b_koff) * 2);
            ldsm4(wHi + off, bh[p]);
            ldsm4(wLo + off, bl[p]);
        }
#pragma unroll
        for (int p = 0; p < 2; ++p)
#pragma unroll
            for (int h = 0; h < 2; ++h)
#pragma unroll
                for (int mt = 0; mt < 2; ++mt) {
                    mma16816(d[mt][p * 2 + h], ah[mt], bh[p][2 * h], bh[p][2 * h + 1]);
                    mma16816(d[mt][p * 2 + h], ah[mt], bl[p][2 * h], bl[p][2 * h + 1]);
                    mma16816(d[mt][p * 2 + h], al[mt], bh[p][2 * h], bh[p][2 * h + 1]);
                }
    }
}

__global__ __launch_bounds__(ETHREADS, 1)
void edge_mlp_mma_kernel(const int* __restrict__ ei,
                         const __nv_bfloat16* __restrict__ xhi,
                         const __nv_bfloat16* __restrict__ xlo,
                         const unsigned char* __restrict__ w1hi, const unsigned char* __restrict__ w1lo,
                         const unsigned char* __restrict__ w2hi, const unsigned char* __restrict__ w2lo,
                         const float* __restrict__ b1, const float* __restrict__ b2,
                         float* __restrict__ agg)
{
    extern __shared__ char smc[];
    float* b1s = (float*)(smc + SM_B1);
    float* b2s = (float*)(smc + SM_B2);

    const int tid  = threadIdx.x;
    const int g    = tid >> 8;          // group 0 (warps 0-7) / 1 (warps 8-15)
    const int tl   = tid & 255;         // thread-in-group
    const int lw   = (tid >> 5) & 7;    // warp-in-group
    const int lane = tid & 31;

    const uint32_t sbase = smem_u32(smc);
    const uint32_t w1Hi = sbase + W1_HI_OFF, w1Lo = sbase + W1_LO_OFF;
    const uint32_t w2Hi = sbase + W2_HI_OFF, w2Lo = sbase + W2_LO_OFF;

    // ---- load ALL weight tiles + biases once per CTA ----
    {
        uint4* d1h = (uint4*)(smc + W1_HI_OFF);
        uint4* d1l = (uint4*)(smc + W1_LO_OFF);
        uint4* d2h = (uint4*)(smc + W2_HI_OFF);
        uint4* d2l = (uint4*)(smc + W2_LO_OFF);
        const uint4* s1h = (const uint4*)w1hi;
        const uint4* s1l = (const uint4*)w1lo;
        const uint4* s2h = (const uint4*)w2hi;
        const uint4* s2l = (const uint4*)w2lo;
        for (int i = tid; i < WTILE_BYTES / 16; i += ETHREADS) {
            d1h[i] = s1h[i]; d1l[i] = s1l[i];
            d2h[i] = s2h[i]; d2l[i] = s2l[i];
        }
        if (tid < 128) { b1s[tid] = b1[tid]; b2s[tid] = b2[tid]; }
    }
    __syncthreads();

    // group-local A buffer + colS
    char* abase = smc + A_OFF + g * 2 * ATILE_BYTES;
    const uint32_t aHi = sbase + A_OFF + g * 2 * ATILE_BYTES;
    const uint32_t aLo = aHi + ATILE_BYTES;
    const int* colS = (const int*)(smc + SM_COLS + g * 256);

    const int mrow = (lw >> 2) * 32;    // 2 warp rows
    const int ncol = (lw & 3) * 32;     // 4 warp cols
    const int crow = lane >> 2;
    const int ccol = (lane & 3) * 2;

    // gather addressing: 4 threads/row, 64B each of hi and lo
    const int gr = tl >> 2;
    const int gc = (tl & 3) * 64;

    for (int t = blockIdx.x * 2 + g; t < NT64; t += 2 * EDGE_GRID) {
        // ---- gather this group's 64-edge tile (cp.async) ----
        {
            const int e0 = t * 64;
            if (tl < 64)
                CP_ASYNC4(sbase + SM_COLS + g * 256 + tl * 4,
                          (const char*)(ei + N_EDGES + e0 + tl));
            const int src = ei[e0 + gr];
            const char* sh = (const char*)(xhi + (size_t)src * D) + gc;
            const char* sl = (const char*)(xlo + (size_t)src * D) + gc;
            const uint32_t dh = aHi + gr * (LDA * 2) + gc;
            const uint32_t dl = dh + ATILE_BYTES;
            CP_ASYNC16(dh,      sh);      CP_ASYNC16(dh + 16, sh + 16);
            CP_ASYNC16(dh + 32, sh + 32); CP_ASYNC16(dh + 48, sh + 48);
            CP_ASYNC16(dl,      sl);      CP_ASYNC16(dl + 16, sl + 16);
            CP_ASYNC16(dl + 32, sl + 32); CP_ASYNC16(dl + 48, sl + 48);
            CP_COMMIT();
            CP_WAIT0();
        }
        GBAR(g);   // A + colS visible to the whole group

        float d[2][4][4];
#pragma unroll
        for (int mt = 0; mt < 2; ++mt)
#pragma unroll
            for (int nt = 0; nt < 4; ++nt)
#pragma unroll
                for (int q = 0; q < 4; ++q) d[mt][nt][q] = 0.f;

        // GEMM1: D1 = A @ W1
        gemm_split32e(aHi, aLo, w1Hi, w1Lo, mrow, ncol, lane, d);
        GBAR(g);   // group done reading A before T overwrites it

        // Epilogue 1: bias+relu, re-split, T -> A buffers (in place)
#pragma unroll
        for (int mt = 0; mt < 2; ++mt) {
#pragma unroll
            for (int nt = 0; nt < 4; ++nt) {
                const int row = mrow + mt * 16 + crow;
                const int col = ncol + nt * 8 + ccol;
                float f0 = fmaxf(d[mt][nt][0] + b1s[col],     0.f);
                float f1 = fmaxf(d[mt][nt][1] + b1s[col + 1], 0.f);
                float f2 = fmaxf(d[mt][nt][2] + b1s[col],     0.f);
                float f3 = fmaxf(d[mt][nt][3] + b1s[col + 1], 0.f);
                uint32_t o0 = (uint32_t)(row * LDA + col) * 2;
                uint32_t o1 = (uint32_t)((row + 8) * LDA + col) * 2;
                *(uint32_t*)(abase + o0) = pack_bf16_hi(f0, f1);
                *(uint32_t*)(abase + o1) = pack_bf16_hi(f2, f3);
                float r0 = f0 - __bfloat162float(__float2bfloat16_rn(f0));
                float r1 = f1 - __bfloat162float(__float2bfloat16_rn(f1));
                float r2 = f2 - __bfloat162float(__float2bfloat16_rn(f2));
                float r3 = f3 - __bfloat162float(__float2bfloat16_rn(f3));
                *(uint32_t*)(abase + ATILE_BYTES + o0) = pack_bf16_hi(r0, r1);
                *(uint32_t*)(abase + ATILE_BYTES + o1) = pack_bf16_hi(r2, r3);
            }
        }
        GBAR(g);   // T visible to the group

#pragma unroll
        for (int mt = 0; mt < 2; ++mt)
#pragma unroll
            for (int nt = 0; nt < 4; ++nt)
#pragma unroll
                for (int q = 0; q < 4; ++q) d[mt][nt][q] = 0.f;

        // GEMM2: D2 = T @ W2
        gemm_split32e(aHi, aLo, w2Hi, w2Lo, mrow, ncol, lane, d);

        // Epilogue 2: bias + red.v2 scatter into agg[col]
#pragma unroll
        for (int mt = 0; mt < 2; ++mt) {
            const int row0 = mrow + mt * 16 + crow;
            const int c0 = colS[row0];
            const int c1 = colS[row0 + 8];
#pragma unroll
            for (int nt = 0; nt < 4; ++nt) {
                const int col = ncol + nt * 8 + ccol;
                red_add_v2(agg + (size_t)c0 * D + col,
                           d[mt][nt][0] + b2s[col], d[mt][nt][1] + b2s[col + 1]);
                red_add_v2(agg + (size_t)c1 * D + col,
                           d[mt][nt][2] + b2s[col], d[mt][nt][3] + b2s[col + 1]);
            }
        }
        GBAR(g);   // all warps past GEMM2/scatter before next gather overwrites
    }
}

// ===========================================================================
// Node MLP via mma.sync (split-bf16, 3-term), K folded to 256 (u -> U' bias).
// ===========================================================================
#define NSM_RCP 0
#define NSM_BAT 512
#define NSM_B1  1024
#define NSM_B2  1536
#define NA_HI   2048
#define NA_LO   (NA_HI + 128 * LDN_B)     // 69632
#define NW_HI   (NA_LO + 128 * LDN_B)     // 137216
#define NW_LO   (NW_HI + WTILE_BYTES)     // 172032
static const int NODE2_SMEM = NW_LO + WTILE_BYTES;   // 206848

// split GEMM over K=128 on 128-row A (stride LDN_B), W stride 272B; warp tile 32x32
__device__ __forceinline__ void gemm_split32n(uint32_t aHi, uint32_t aLo,
                                              uint32_t wHi, uint32_t wLo,
                                              int mrow, int ncol, int lane,
                                              float d[2][4][4]) {
    const int a_row  = lane & 15;
    const int a_koff = (lane >> 4) << 3;
    const int b_nrow = ((lane >> 4) << 3) + (lane & 7);
    const int b_koff = ((lane >> 3) & 1) << 3;
#pragma unroll
    for (int ks = 0; ks < 8; ++ks) {
        const int kb = ks * 16;
        uint32_t ah[2][4], al[2][4], bh[2][4], bl[2][4];
#pragma unroll
        for (int mt = 0; mt < 2; ++mt) {
            uint32_t off = (uint32_t)((mrow + mt * 16 + a_row) * LDN_B + (kb + a_koff) * 2);
            ldsm4(aHi + off, ah[mt]);
            ldsm4(aLo + off, al[mt]);
        }
#pragma unroll
        for (int p = 0; p < 2; ++p) {
            uint32_t off = (uint32_t)(((ncol + p * 16 + b_nrow) * LDA + kb + b_koff) * 2);
            ldsm4(wHi + off, bh[p]);
            ldsm4(wLo + off, bl[p]);
        }
#pragma unroll
        for (int p = 0; p < 2; ++p)
#pragma unroll
            for (int h = 0; h < 2; ++h)
#pragma unroll
                for (int mt = 0; mt < 2; ++mt) {
                    mma16816(d[mt][p * 2 + h], ah[mt], bh[p][2 * h], bh[p][2 * h + 1]);
                    mma16816(d[mt][p * 2 + h], ah[mt], bl[p][2 * h], bl[p][2 * h + 1]);
                    mma16816(d[mt][p * 2 + h], al[mt], bh[p][2 * h], bh[p][2 * h + 1]);
                }
    }
}

__global__ __launch_bounds__(512, 1)
void node_mlp_mma_kernel(const float* __restrict__ agg,
                         const float* __restrict__ cnt,
                         const int* __restrict__ batch,
                         const __nv_bfloat16* __restrict__ xhi_r,
                         const __nv_bfloat16* __restrict__ xlo_r,
                         const unsigned char* __restrict__ wbase,  // W1a hi/lo, W1b hi/lo, W2 hi/lo
                         const float* __restrict__ b1, const float* __restrict__ b2,
                         const float* __restrict__ uprime,
                         float* __restrict__ xout, float* __restrict__ xsum,
                         __nv_bfloat16* __restrict__ xhi_w,
                         __nv_bfloat16* __restrict__ xlo_w)
{
    extern __shared__ char smc[];
    float* rcp = (float*)(smc + NSM_RCP);
    int*   bat = (int*)(smc + NSM_BAT);
    float* b1s = (float*)(smc + NSM_B1);
    float* b2s = (float*)(smc + NSM_B2);

    const uint32_t sbase = smem_u32(smc);
    const uint32_t aHi = sbase + NA_HI, aLo = sbase + NA_LO;
    const uint32_t wHi = sbase + NW_HI, wLo = sbase + NW_LO;

    const int tid = threadIdx.x, warp = tid >> 5, lane = tid & 31;
    const int n0 = blockIdx.x * 128;

    if (tid < 128) {
        int n = n0 + tid;
        if (n < N_NODES) { rcp[tid] = 1.f / fmaxf(cnt[n], 1.f); bat[tid] = batch[n]; }
        else             { rcp[tid] = 0.f; bat[tid] = 0; }
        b1s[tid] = b1[tid]; b2s[tid] = b2[tid];
    }
    {
        uint4* dw = (uint4*)(smc + NW_HI);
        const uint4* sw = (const uint4*)wbase;
        for (int i = tid; i < (2 * WTILE_BYTES) / 16; i += 512) dw[i] = sw[i];
    }
    __syncthreads();

    for (int idx = tid; idx < 128 * 16; idx += 512) {
        int r = idx >> 4, q = idx & 15;
        int n = n0 + r;
        uint4 h = make_uint4(0, 0, 0, 0), l = make_uint4(0, 0, 0, 0);
        if (n < N_NODES) {
            h = *(const uint4*)(xhi_r + (size_t)n * D + q * 8);
            l = *(const uint4*)(xlo_r + (size_t)n * D + q * 8);
        }
        *(uint4*)(smc + NA_HI + r * LDN_B + q * 16) = h;
        *(uint4*)(smc + NA_LO + r * LDN_B + q * 16) = l;
    }
    for (int idx = tid; idx < 128 * 64; idx += 512) {
        int r = idx >> 6, c2 = idx & 63;
        int n = n0 + r;
        float2 v = make_float2(0.f, 0.f);
        if (n < N_NODES) v = *(const float2*)(agg + (size_t)n * D + c2 * 2);
        float s = rcp[r];
        v.x *= s; v.y *= s;
        float l0 = v.x - __bfloat162float(__float2bfloat16_rn(v.x));
        float l1 = v.y - __bfloat162float(__float2bfloat16_rn(v.y));
        *(uint32_t*)(smc + NA_HI + r * LDN_B + 256 + c2 * 4) = pack_bf16_hi(v.x, v.y);
        *(uint32_t*)(smc + NA_LO + r * LDN_B + 256 + c2 * 4) = pack_bf16_hi(l0, l1);
    }
    __syncthreads();

    const int mrow = (warp >> 2) * 32;
    const int ncol = (warp & 3) * 32;
    const int crow = lane >> 2, ccol = (lane & 3) * 2;

    float d[2][4][4];
#pragma unroll
    for (int mt = 0; mt < 2; ++mt)
#pragma unroll
        for (int nt = 0; nt < 4; ++nt)
#pragma unroll
            for (int q = 0; q < 4; ++q) d[mt][nt][q] = 0.f;

    gemm_split32n(aHi, aLo, wHi, wLo, mrow, ncol, lane, d);
    __syncthreads();
    {
        uint4* dw = (uint4*)(smc + NW_HI);
        const uint4* sw = (const uint4*)(wbase + 2 * WTILE_BYTES);
        for (int i = tid; i < (2 * WTILE_BYTES) / 16; i += 512) dw[i] = sw[i];
    }
    __syncthreads();
    gemm_split32n(aHi + 256, aLo + 256, wHi, wLo, mrow, ncol, lane, d);

#pragma unroll
    for (int mt = 0; mt < 2; ++mt) {
        const int r0 = mrow + mt * 16 + crow, r1 = r0 + 8;
        const int bb0 = bat[r0], bb1 = bat[r1];
#pragma unroll
        for (int nt = 0; nt < 4; ++nt) {
            const int col = ncol + nt * 8 + ccol;
            float2 u0 = *(const float2*)(uprime + (size_t)bb0 * D + col);
            float2 u1 = *(const float2*)(uprime + (size_t)bb1 * D + col);
            float f0 = fmaxf(d[mt][nt][0] + b1s[col]     + u0.x, 0.f);
            float f1 = fmaxf(d[mt][nt][1] + b1s[col + 1] + u0.y, 0.f);
            float f2 = fmaxf(d[mt][nt][2] + b1s[col]     + u1.x, 0.f);
            float f3 = fmaxf(d[mt][nt][3] + b1s[col + 1] + u1.y, 0.f);
            uint32_t o0 = (uint32_t)(r0 * LDN_B + col * 2);
            uint32_t o1 = (uint32_t)(r1 * LDN_B + col * 2);
            *(uint32_t*)(smc + NA_HI + o0) = pack_bf16_hi(f0, f1);
            *(uint32_t*)(smc + NA_HI + o1) = pack_bf16_hi(f2, f3);
            float l0 = f0 - __bfloat162float(__float2bfloat16_rn(f0));
            float l1 = f1 - __bfloat162float(__float2bfloat16_rn(f1));
            float l2 = f2 - __bfloat162float(__float2bfloat16_rn(f2));
            float l3 = f3 - __bfloat162float(__float2bfloat16_rn(f3));
            *(uint32_t*)(smc + NA_LO + o0) = pack_bf16_hi(l0, l1);
            *(uint32_t*)(smc + NA_LO + o1) = pack_bf16_hi(l2, l3);
        }
    }
    __syncthreads();
    {
        uint4* dw = (uint4*)(smc + NW_HI);
        const uint4* sw = (const uint4*)(wbase + 4 * WTILE_BYTES);
        for (int i = tid; i < (2 * WTILE_BYTES) / 16; i += 512) dw[i] = sw[i];
    }
    __syncthreads();

#pragma unroll
    for (int mt = 0; mt < 2; ++mt)
#pragma unroll
        for (int nt = 0; nt < 4; ++nt)
#pragma unroll
            for (int q = 0; q < 4; ++q) d[mt][nt][q] = 0.f;

    gemm_split32n(aHi, aLo, wHi, wLo, mrow, ncol, lane, d);

#pragma unroll
    for (int mt = 0; mt < 2; ++mt) {
        const int r0 = mrow + mt * 16 + crow, r1 = r0 + 8;
        const int nn0 = n0 + r0, nn1 = n0 + r1;
        const int bb0 = bat[r0], bb1 = bat[r1];
#pragma unroll
        for (int nt = 0; nt < 4; ++nt) {
            const int col = ncol + nt * 8 + ccol;
            float o0 = d[mt][nt][0] + b2s[col];
            float o1 = d[mt][nt][1] + b2s[col + 1];
            float o2 = d[mt][nt][2] + b2s[col];
            float o3 = d[mt][nt][3] + b2s[col + 1];
            if (nn0 < N_NODES) {
                *(float2*)(xout + (size_t)nn0 * D + col) = make_float2(o0, o1);
                *(uint32_t*)(xhi_w + (size_t)nn0 * D + col) = pack_bf16_hi(o0, o1);
                float l0 = o0 - __bfloat162float(__float2bfloat16_rn(o0));
                float l1 = o1 - __bfloat162float(__float2bfloat16_rn(o1));
                *(uint32_t*)(xlo_w + (size_t)nn0 * D + col) = pack_bf16_hi(l0, l1);
                red_add_v2(xsum + (size_t)bb0 * D + col, o0, o1);
            }
            if (nn1 < N_NODES) {
                *(float2*)(xout + (size_t)nn1 * D + col) = make_float2(o2, o3);
                *(uint32_t*)(xhi_w + (size_t)nn1 * D + col) = pack_bf16_hi(o2, o3);
                float l2 = o2 - __bfloat162float(__float2bfloat16_rn(o2));
                float l3 = o3 - __bfloat162float(__float2bfloat16_rn(o3));
                *(uint32_t*)(xlo_w + (size_t)nn1 * D + col) = pack_bf16_hi(l2, l3);
                red_add_v2(xsum + (size_t)bb1 * D + col, o2, o3);
            }
        }
    }
}

// ===========================================================================
// Global MLP (unchanged)
// ===========================================================================
__global__ __launch_bounds__(256, 1)
void global_mlp_kernel(const float* __restrict__ u,
                       const float* __restrict__ xsum,
                       const float* __restrict__ bcnt,
                       const float* __restrict__ w1, const float* __restrict__ b1,
                       const float* __restrict__ w2, const float* __restrict__ b2,
                       float* __restrict__ uout)
{
    extern __shared__ float sm[];
    float* G  = sm;              // [64][256]
    float* Hh = G + 64 * 256;    // [64][EPAD]

    const int tid = threadIdx.x;
    const int tx  = tid & 15;
    const int ty  = tid >> 4;

    for (int idx = tid; idx < 64 * 128; idx += 256) {
        int b = idx >> 7, c = idx & 127;
        G[b * 256 + c]       = u[idx];
        G[b * 256 + 128 + c] = xsum[idx] / fmaxf(bcnt[b], 1.0f);
    }
    __syncthreads();

    float acc[4][8];
#pragma unroll
    for (int i = 0; i < 4; ++i)
#pragma unroll
        for (int j = 0; j < 8; ++j) acc[i][j] = 0.f;

#pragma unroll 4
    for (int k = 0; k < 256; ++k) {
        float ra[4];
#pragma unroll
        for (int i = 0; i < 4; ++i) ra[i] = G[(ty * 4 + i) * 256 + k];
        float4 rb0 = __ldg((const float4*)&w1[k * 128 + tx * 8]);
        float4 rb1 = __ldg((const float4*)&w1[k * 128 + tx * 8 + 4]);
        float rb[8] = {rb0.x, rb0.y, rb0.z, rb0.w, rb1.x, rb1.y, rb1.z, rb1.w};
#pragma unroll
        for (int i = 0; i < 4; ++i)
#pragma unroll
            for (int j = 0; j < 8; ++j) acc[i][j] = fmaf(ra[i], rb[j], acc[i][j]);
    }

    {
        float bv[8];
#pragma unroll
        for (int j = 0; j < 8; ++j) bv[j] = b1[tx * 8 + j];
#pragma unroll
        for (int i = 0; i < 4; ++i) {
#pragma unroll
            for (int j = 0; j < 8; ++j) acc[i][j] = fmaxf(acc[i][j] + bv[j], 0.f);
            *(float4*)&Hh[(ty * 4 + i) * EPAD + tx * 8]     = make_float4(acc[i][0], acc[i][1], acc[i][2], acc[i][3]);
            *(float4*)&Hh[(ty * 4 + i) * EPAD + tx * 8 + 4] = make_float4(acc[i][4], acc[i][5], acc[i][6], acc[i][7]);
        }
    }
    __syncthreads();

#pragma unroll
    for (int i = 0; i < 4; ++i)
#pragma unroll
        for (int j = 0; j < 8; ++j) acc[i][j] = 0.f;

#pragma unroll 4
    for (int k = 0; k < 128; ++k) {
        float ra[4];
#pragma unroll
        for (int i = 0; i < 4; ++i) ra[i] = Hh[(ty * 4 + i) * EPAD + k];
        float4 rb0 = __ldg((const float4*)&w2[k * 128 + tx * 8]);
        float4 rb1 = __ldg((const float4*)&w2[k * 128 + tx * 8 + 4]);
        float rb[8] = {rb0.x, rb0.y, rb0.z, rb0.w, rb1.x, rb1.y, rb1.z, rb1.w};
#pragma unroll
        for (int i = 0; i < 4; ++i)
#pragma unroll
            for (int j = 0; j < 8; ++j) acc[i][j] = fmaf(ra[i], rb[j], acc[i][j]);
    }

    {
        float bv[8];
#pragma unroll
        for (int j = 0; j < 8; ++j) bv[j] = b2[tx * 8 + j];
#pragma unroll
        for (int i = 0; i < 4; ++i) {
            int b = ty * 4 + i;
            *(float4*)&uout[b * D + tx * 8]     = make_float4(acc[i][0] + bv[0], acc[i][1] + bv[1],
                                                              acc[i][2] + bv[2], acc[i][3] + bv[3]);
            *(float4*)&uout[b * D + tx * 8 + 4] = make_float4(acc[i][4] + bv[4], acc[i][5] + bv[5],
                                                              acc[i][6] + bv[6], acc[i][7] + bv[7]);
        }
    }
}

// ===========================================================================
// Host side
// ===========================================================================
static const int GLOB_SMEM = (64 * 256 + 64 * EPAD) * 4;

extern "C" void kernel_launch(void* const* d_in, const int* in_sizes, int n_in,
                              void* d_out, int out_size) {
    const float* x0    = (const float*)d_in[0];
    const int*   ei    = (const int*)d_in[1];      // int32 (JAX x64 disabled)
    const float* u0    = (const float*)d_in[2];
    const int*   batch = (const int*)d_in[3];      // int32
    const float* n1w1 = (const float*)d_in[4];
    const float* n1b1 = (const float*)d_in[5];
    const float* n1w2 = (const float*)d_in[6];
    const float* n1b2 = (const float*)d_in[7];
    const float* n2w1 = (const float*)d_in[8];
    const float* n2b1 = (const float*)d_in[9];
    const float* n2w2 = (const float*)d_in[10];
    const float* n2b2 = (const float*)d_in[11];
    const float* gw1  = (const float*)d_in[12];
    const float* gb1  = (const float*)d_in[13];
    const float* gw2  = (const float*)d_in[14];
    const float* gb2  = (const float*)d_in[15];
    float* out = (float*)d_out;

    float *px, *pu, *pagg, *pcnt, *pxsum, *pbcnt, *pup;
    unsigned char* pwt;
    __nv_bfloat16 *pxhi, *pxlo;
    cudaGetSymbolAddress((void**)&px,    g_x);
    cudaGetSymbolAddress((void**)&pu,    g_u);
    cudaGetSymbolAddress((void**)&pagg,  g_agg);
    cudaGetSymbolAddress((void**)&pcnt,  g_cnt);
    cudaGetSymbolAddress((void**)&pxsum, g_xsum);
    cudaGetSymbolAddress((void**)&pbcnt, g_bcnt);
    cudaGetSymbolAddress((void**)&pup,   g_uprime);
    cudaGetSymbolAddress((void**)&pwt,   g_wt);
    cudaGetSymbolAddress((void**)&pxhi,  g_xhi);
    cudaGetSymbolAddress((void**)&pxlo,  g_xlo);
    float* xbuf[2] = {px, px + (size_t)N_NODES * D};
    float* ubuf[2] = {pu, pu + (size_t)NB * D};
    __nv_bfloat16* xhib[2] = {pxhi, pxhi + (size_t)N_NODES * D};
    __nv_bfloat16* xlob[2] = {pxlo, pxlo + (size_t)N_NODES * D};

    cudaFuncSetAttribute(edge_mlp_mma_kernel, cudaFuncAttributeMaxDynamicSharedMemorySize, EDGE_SMEM);
    cudaFuncSetAttribute(node_mlp_mma_kernel, cudaFuncAttributeMaxDynamicSharedMemorySize, NODE2_SMEM);
    cudaFuncSetAttribute(global_mlp_kernel,   cudaFuncAttributeMaxDynamicSharedMemorySize, GLOB_SMEM);

    // one-time: counts + weight tiles + layer-0 x split
    cudaMemsetAsync(pcnt,  0, N_NODES * sizeof(float));
    cudaMemsetAsync(pbcnt, 0, NB * sizeof(float));
    count_edges_kernel<<<(N_EDGES + 255) / 256, 256>>>(ei, pcnt);
    count_batch_kernel<<<(N_NODES + 255) / 256, 256>>>(batch, pbcnt);
    prep_weights_kernel<<<20, 256>>>(n1w1, n1w2, n2w1, n2w2);
    split_x_kernel<<<(N_NODES * (D / 2) + 255) / 256, 256>>>(x0);

    const float* uc = u0;
    for (int l = 0; l < NLAYERS; ++l) {
        const int rd = l & 1, wr = rd ^ 1;
        cudaMemsetAsync(pagg,  0, (size_t)N_NODES * D * sizeof(float));
        cudaMemsetAsync(pxsum, 0, (size_t)NB * D * sizeof(float));

        const unsigned char* ew1hi = pwt + (size_t)(l * 4 + 0) * WTILE_BYTES;
        const unsigned char* ew1lo = pwt + (size_t)(l * 4 + 1) * WTILE_BYTES;
        const unsigned char* ew2hi = pwt + (size_t)(l * 4 + 2) * WTILE_BYTES;
        const unsigned char* ew2lo = pwt + (size_t)(l * 4 + 3) * WTILE_BYTES;
        const unsigned char* nwb   = pwt + (size_t)(16 + l * 6) * WTILE_BYTES;

        edge_mlp_mma_kernel<<<EDGE_GRID, ETHREADS, EDGE_SMEM>>>(
            ei, xhib[rd], xlob[rd], ew1hi, ew1lo, ew2hi, ew2lo,
            n1b1 + (size_t)l * D, n1b2 + (size_t)l * D, pagg);

        uprime_kernel<<<NB, 128>>>(uc, n2w1 + (size_t)l * 384 * D + 256 * D);

        float* xn = (l == NLAYERS - 1) ? out : xbuf[l & 1];
        node_mlp_mma_kernel<<<NT_NODE, 512, NODE2_SMEM>>>(
            pagg, pcnt, batch, xhib[rd], xlob[rd], nwb,
            n2b1 + (size_t)l * D, n2b2 + (size_t)l * D, pup,
            xn, pxsum, xhib[wr], xlob[wr]);

        float* un = (l == NLAYERS - 1) ? out + (size_t)N_NODES * D : ubuf[l & 1];
        global_mlp_kernel<<<1, 256, GLOB_SMEM>>>(
            uc, pxsum, pbcnt,
            gw1 + (size_t)l * 256 * D, gb1 + (size_t)l * D,
            gw2 + (size_t)l * D * D,   gb2 + (size_t)l * D,
            un);

        uc = un;
    }
}

// round 16
// speedup vs baseline: 1.8642x; 1.3325x over previous
#include <cuda_runtime.h>
#include <cuda_bf16.h>
#include <cstdint>

#define N_NODES 50000
#define N_EDGES 600000
#define NB      64
#define D       128      // F == H == U
#define NLAYERS 4

#define EPAD 132   // padded row stride for 128-wide smem tiles (global mlp)

#define LDA 136                      // bf16 row stride for W/edge-A tiles (272B)
#define WTILE_BYTES (128 * LDA * 2)  // 34816 bytes per 128x128 bf16 tile
#define ATILE_BYTES (64 * LDA * 2)   // 17408 bytes per 64x128 bf16 tile
#define NT64 (N_EDGES / 64)          // 9375 edge tiles, exact
#define NT_NODE ((N_NODES + 127) / 128)  // 391 node tiles
#define LDN_B 528                    // node A row stride bytes (264 bf16)

// ===========================================================================
// Scratch (no allocations allowed -> __device__ globals)
// ===========================================================================
__device__ float g_x[2][N_NODES * D];
__device__ float g_u[2][NB * D];
__device__ float g_agg[N_NODES * D];         // now holds Tagg (scatter of relu'd hidden)
__device__ float g_cnt[N_NODES];
__device__ float g_xsum[NB * D];
__device__ float g_bcnt[NB];
__device__ float g_uprime[NB * D];
__device__ float g_wc[NLAYERS][D * D];       // Wc = n1w2 @ W1b (fp32)
__device__ float g_bc[NLAYERS][D];           // bc = n1b2 @ W1b
// x pre-split into bf16 hi/lo, DOUBLE BUFFERED
__device__ __align__(16) __nv_bfloat16 g_xhi[2][N_NODES * D];
__device__ __align__(16) __nv_bfloat16 g_xlo[2][N_NODES * D];
// transposed/split bf16 weight tiles [n][k]:
//  tiles 0..15 : edge  (layer, w1/w2, hi/lo)   (w2 slots now unused but kept)
//  tiles 16..39: node  (layer, {W1a, Wc, W2}, hi/lo)
__device__ __align__(16) unsigned char g_wt[40 * WTILE_BYTES];

__device__ __forceinline__ void red_add_v2(float* addr, float a, float b) {
    asm volatile("red.global.add.v2.f32 [%0], {%1,%2};"
                 :: "l"(addr), "f"(a), "f"(b) : "memory");
}

__device__ __forceinline__ uint32_t smem_u32(const void* p) {
    uint32_t a;
    asm("{ .reg .u64 t; cvta.to.shared.u64 t, %1; cvt.u32.u64 %0, t; }" : "=r"(a) : "l"(p));
    return a;
}

__device__ __forceinline__ void ldsm4(uint32_t addr, uint32_t r[4]) {
    asm volatile("ldmatrix.sync.aligned.m8n8.x4.shared.b16 {%0,%1,%2,%3}, [%4];"
                 : "=r"(r[0]), "=r"(r[1]), "=r"(r[2]), "=r"(r[3]) : "r"(addr));
}

__device__ __forceinline__ void mma16816(float d[4], const uint32_t a[4],
                                         uint32_t b0, uint32_t b1) {
    asm volatile(
        "mma.sync.aligned.m16n8k16.row.col.f32.bf16.bf16.f32 "
        "{%0,%1,%2,%3}, {%4,%5,%6,%7}, {%8,%9}, {%0,%1,%2,%3};"
        : "+f"(d[0]), "+f"(d[1]), "+f"(d[2]), "+f"(d[3])
        : "r"(a[0]), "r"(a[1]), "r"(a[2]), "r"(a[3]), "r"(b0), "r"(b1));
}

__device__ __forceinline__ uint32_t pack_bf16_hi(float f0, float f1) {
    return ((uint32_t)__bfloat16_as_ushort(__float2bfloat16_rn(f1)) << 16)
         |  (uint32_t)__bfloat16_as_ushort(__float2bfloat16_rn(f0));
}

#define CP_ASYNC16(dst, src) \
    asm volatile("cp.async.ca.shared.global [%0], [%1], 16;" :: "r"(dst), "l"(src) : "memory")
#define CP_ASYNC4(dst, src) \
    asm volatile("cp.async.ca.shared.global [%0], [%1], 4;"  :: "r"(dst), "l"(src) : "memory")
#define CP_COMMIT() asm volatile("cp.async.commit_group;" ::: "memory")
#define CP_WAIT0()  asm volatile("cp.async.wait_group 0;"  ::: "memory")
#define GBAR(g) asm volatile("bar.sync %0, 256;" :: "r"((g) + 1) : "memory")

// ===========================================================================
// One-time kernels
// ===========================================================================
__global__ void count_edges_kernel(const int* __restrict__ ei, float* __restrict__ cnt) {
    int e = blockIdx.x * 256 + threadIdx.x;
    if (e < N_EDGES) atomicAdd(&cnt[ei[N_EDGES + e]], 1.0f);
}
__global__ void count_batch_kernel(const int* __restrict__ batch, float* __restrict__ bcnt) {
    int n = blockIdx.x * 256 + threadIdx.x;
    if (n < N_NODES) atomicAdd(&bcnt[batch[n]], 1.0f);
}

__global__ void split_x_kernel(const float* __restrict__ x) {
    int i = blockIdx.x * 256 + threadIdx.x;
    if (i < N_NODES * (D / 2)) {
        float2 v = ((const float2*)x)[i];
        ((uint32_t*)g_xhi[0])[i] = pack_bf16_hi(v.x, v.y);
        float l0 = v.x - __bfloat162float(__float2bfloat16_rn(v.x));
        float l1 = v.y - __bfloat162float(__float2bfloat16_rn(v.y));
        ((uint32_t*)g_xlo[0])[i] = pack_bf16_hi(l0, l1);
    }
}

// Wc = n1w2 @ W1b  and  bc = n1b2 @ W1b  (fp32). grid = NLAYERS*128, block 128.
__global__ void wc_kernel(const float* __restrict__ n1w2,
                          const float* __restrict__ n2w1,
                          const float* __restrict__ n1b2) {
    int l = blockIdx.x >> 7, k = blockIdx.x & 127, n = threadIdx.x;
    const float* w2  = n1w2 + (size_t)l * D * D;
    const float* w1b = n2w1 + (size_t)l * 384 * D + (size_t)128 * D;
    float s = 0.f;
#pragma unroll 4
    for (int j = 0; j < D; ++j)
        s = fmaf(w2[k * D + j], __ldg(&w1b[j * D + n]), s);
    g_wc[l][k * D + n] = s;
    if (k == 0) {
        float t = 0.f;
#pragma unroll 4
        for (int j = 0; j < D; ++j)
            t = fmaf(n1b2[l * D + j], __ldg(&w1b[j * D + n]), t);
        g_bc[l][n] = t;
    }
}

// Transpose+split weights into bf16 hi/lo tiles [n][k], LDA pad.
// blocks 0..7 : edge  (l=b>>1, which -> n1w1/n1w2)
// blocks 8..19: node  (bb=b-8: l=bb/3, j=bb%3 -> W1a, Wc, W2)
__global__ void prep_weights_kernel(const float* __restrict__ n1w1,
                                    const float* __restrict__ n1w2,
                                    const float* __restrict__ n2w1,
                                    const float* __restrict__ n2w2) {
    int b = blockIdx.x;
    const float* w;
    unsigned char *thi, *tlo;
    if (b < 8) {
        int l = b >> 1, which = b & 1;
        w = (which ? n1w2 : n1w1) + (size_t)l * D * D;
        thi = g_wt + (size_t)(b * 2) * WTILE_BYTES;
    } else {
        int bb = b - 8, l = bb / 3, j = bb % 3;
        w = (j == 0) ? n2w1 + (size_t)l * 384 * D
          : (j == 1) ? g_wc[l]
                     : n2w2 + (size_t)l * D * D;
        thi = g_wt + (size_t)(16 + (l * 3 + j) * 2) * WTILE_BYTES;
    }
    tlo = thi + WTILE_BYTES;
    for (int idx = threadIdx.x; idx < 128 * 32; idx += 256) {
        int n = idx >> 5, kq = (idx & 31) << 2;
        unsigned short hh[4], ll[4];
#pragma unroll
        for (int q = 0; q < 4; ++q) {
            float f = w[(kq + q) * D + n];
            __nv_bfloat16 h = __float2bfloat16_rn(f);
            float r = f - __bfloat162float(h);
            hh[q] = __bfloat16_as_ushort(h);
            ll[q] = __bfloat16_as_ushort(__float2bfloat16_rn(r));
        }
        uint32_t o = (uint32_t)(n * LDA + kq) * 2;
        *(uint2*)(thi + o) = make_uint2(((uint32_t)hh[1] << 16) | hh[0],
                                        ((uint32_t)hh[3] << 16) | hh[2]);
        *(uint2*)(tlo + o) = make_uint2(((uint32_t)ll[1] << 16) | ll[0],
                                        ((uint32_t)ll[3] << 16) | ll[2]);
    }
}

// U' = u @ W1[256:384]
__global__ void uprime_kernel(const float* __restrict__ u, const float* __restrict__ w1u) {
    __shared__ float us[128];
    int b = blockIdx.x;
    if (threadIdx.x < 128) us[threadIdx.x] = u[b * D + threadIdx.x];
    __syncthreads();
    int n = threadIdx.x;
    float s = 0.f;
#pragma unroll 4
    for (int k = 0; k < 128; ++k)
        s = fmaf(us[k], __ldg(&w1u[k * D + n]), s);
    g_uprime[b * D + n] = s;
}

// ===========================================================================
// Edge kernel: T_e = relu(x[row]@W1 + b1); Tagg[col] += T_e.
// (GEMM2 folded into node side via Wc = W2@W1b.)
// Persistent CTAs, resident W1, two independent 8-warp groups.
// ===========================================================================
#define SM_COLS   0                               // int[2][64]
#define SM_B1     512
#define A_OFF     2048                            // [group][hi,lo] 4 x ATILE
#define W1_HI_OFF (A_OFF + 4 * ATILE_BYTES)
#define W1_LO_OFF (W1_HI_OFF + WTILE_BYTES)
static const int EDGE_SMEM = W1_LO_OFF + WTILE_BYTES;   // 141312
#define ETHREADS 512
#define EDGE_GRID 148

// split GEMM over K=128 on 64-row A (stride 272B): warp tile 32x32
__device__ __forceinline__ void gemm_split32e(uint32_t aHi, uint32_t aLo,
                                              uint32_t wHi, uint32_t wLo,
                                              int mrow, int ncol, int lane,
                                              float d[2][4][4]) {
    const int a_row  = lane & 15;
    const int a_koff = (lane >> 4) << 3;
    const int b_nrow = ((lane >> 4) << 3) + (lane & 7);
    const int b_koff = ((lane >> 3) & 1) << 3;
#pragma unroll
    for (int ks = 0; ks < 8; ++ks) {
        const int kb = ks * 16;
        uint32_t ah[2][4], al[2][4], bh[2][4], bl[2][4];
#pragma unroll
        for (int mt = 0; mt < 2; ++mt) {
            uint32_t off = (uint32_t)(((mrow + mt * 16 + a_row) * LDA + kb + a_koff) * 2);
            ldsm4(aHi + off, ah[mt]);
            ldsm4(aLo + off, al[mt]);
        }
#pragma unroll
        for (int p = 0; p < 2; ++p) {
            uint32_t off = (uint32_t)(((ncol + p * 16 + b_nrow) * LDA + kb + b_koff) * 2);
            ldsm4(wHi + off, bh[p]);
            ldsm4(wLo + off, bl[p]);
        }
#pragma unroll
        for (int p = 0; p < 2; ++p)
#pragma unroll
            for (int h = 0; h < 2; ++h)
#pragma unroll
                for (int mt = 0; mt < 2; ++mt) {
                    mma16816(d[mt][p * 2 + h], ah[mt], bh[p][2 * h], bh[p][2 * h + 1]);
                    mma16816(d[mt][p * 2 + h], ah[mt], bl[p][2 * h], bl[p][2 * h + 1]);
                    mma16816(d[mt][p * 2 + h], al[mt], bh[p][2 * h], bh[p][2 * h + 1]);
                }
    }
}

__global__ __launch_bounds__(ETHREADS, 1)
void edge_mlp_mma_kernel(const int* __restrict__ ei,
                         const __nv_bfloat16* __restrict__ xhi,
                         const __nv_bfloat16* __restrict__ xlo,
                         const unsigned char* __restrict__ w1hi, const unsigned char* __restrict__ w1lo,
                         const float* __restrict__ b1,
                         float* __restrict__ tagg)
{
    extern __shared__ char smc[];
    float* b1s = (float*)(smc + SM_B1);

    const int tid  = threadIdx.x;
    const int g    = tid >> 8;
    const int tl   = tid & 255;
    const int lw   = (tid >> 5) & 7;
    const int lane = tid & 31;

    const uint32_t sbase = smem_u32(smc);
    const uint32_t w1Hi = sbase + W1_HI_OFF, w1Lo = sbase + W1_LO_OFF;

    {
        uint4* d1h = (uint4*)(smc + W1_HI_OFF);
        uint4* d1l = (uint4*)(smc + W1_LO_OFF);
        const uint4* s1h = (const uint4*)w1hi;
        const uint4* s1l = (const uint4*)w1lo;
        for (int i = tid; i < WTILE_BYTES / 16; i += ETHREADS) {
            d1h[i] = s1h[i]; d1l[i] = s1l[i];
        }
        if (tid < 128) b1s[tid] = b1[tid];
    }
    __syncthreads();

    const uint32_t aHi = sbase + A_OFF + g * 2 * ATILE_BYTES;
    const uint32_t aLo = aHi + ATILE_BYTES;
    const int* colS = (const int*)(smc + SM_COLS + g * 256);

    const int mrow = (lw >> 2) * 32;
    const int ncol = (lw & 3) * 32;
    const int crow = lane >> 2;
    const int ccol = (lane & 3) * 2;

    const int gr = tl >> 2;
    const int gc = (tl & 3) * 64;

    for (int t = blockIdx.x * 2 + g; t < NT64; t += 2 * EDGE_GRID) {
        // gather 64-edge tile (cp.async)
        {
            const int e0 = t * 64;
            if (tl < 64)
                CP_ASYNC4(sbase + SM_COLS + g * 256 + tl * 4,
                          (const char*)(ei + N_EDGES + e0 + tl));
            const int src = ei[e0 + gr];
            const char* sh = (const char*)(xhi + (size_t)src * D) + gc;
            const char* sl = (const char*)(xlo + (size_t)src * D) + gc;
            const uint32_t dh = aHi + gr * (LDA * 2) + gc;
            const uint32_t dl = dh + ATILE_BYTES;
            CP_ASYNC16(dh,      sh);      CP_ASYNC16(dh + 16, sh + 16);
            CP_ASYNC16(dh + 32, sh + 32); CP_ASYNC16(dh + 48, sh + 48);
            CP_ASYNC16(dl,      sl);      CP_ASYNC16(dl + 16, sl + 16);
            CP_ASYNC16(dl + 32, sl + 32); CP_ASYNC16(dl + 48, sl + 48);
            CP_COMMIT();
            CP_WAIT0();
        }
        GBAR(g);

        float d[2][4][4];
#pragma unroll
        for (int mt = 0; mt < 2; ++mt)
#pragma unroll
            for (int nt = 0; nt < 4; ++nt)
#pragma unroll
                for (int q = 0; q < 4; ++q) d[mt][nt][q] = 0.f;

        gemm_split32e(aHi, aLo, w1Hi, w1Lo, mrow, ncol, lane, d);

        // Epilogue: T = relu(d + b1), red.v2 scatter into Tagg[col]
#pragma unroll
        for (int mt = 0; mt < 2; ++mt) {
            const int row0 = mrow + mt * 16 + crow;
            const int c0 = colS[row0];
            const int c1 = colS[row0 + 8];
#pragma unroll
            for (int nt = 0; nt < 4; ++nt) {
                const int col = ncol + nt * 8 + ccol;
                red_add_v2(tagg + (size_t)c0 * D + col,
                           fmaxf(d[mt][nt][0] + b1s[col],     0.f),
                           fmaxf(d[mt][nt][1] + b1s[col + 1], 0.f));
                red_add_v2(tagg + (size_t)c1 * D + col,
                           fmaxf(d[mt][nt][2] + b1s[col],     0.f),
                           fmaxf(d[mt][nt][3] + b1s[col + 1], 0.f));
            }
        }
        GBAR(g);   // group done with A + colS before next gather overwrites
    }
}

// ===========================================================================
// Node MLP via mma.sync: h = relu(x@W1a + Tmean@Wc + U'[bat] + b1 + bc*(cnt>0))
//                        x' = h@W2 + b2
// ===========================================================================
#define NSM_RCP 0
#define NSM_BAT 512
#define NSM_B1  1024
#define NSM_B2  1536
#define NSM_CF  2048                      // cnt>0 flag (float 0/1)
#define NSM_BC  2560                      // bc vector
#define NA_HI   3072
#define NA_LO   (NA_HI + 128 * LDN_B)     // 70656
#define NW_HI   (NA_LO + 128 * LDN_B)     // 138240
#define NW_LO   (NW_HI + WTILE_BYTES)     // 173056
static const int NODE2_SMEM = NW_LO + WTILE_BYTES;   // 207872

__device__ __forceinline__ void gemm_split32n(uint32_t aHi, uint32_t aLo,
                                              uint32_t wHi, uint32_t wLo,
                                              int mrow, int ncol, int lane,
                                              float d[2][4][4]) {
    const int a_row  = lane & 15;
    const int a_koff = (lane >> 4) << 3;
    const int b_nrow = ((lane >> 4) << 3) + (lane & 7);
    const int b_koff = ((lane >> 3) & 1) << 3;
#pragma unroll
    for (int ks = 0; ks < 8; ++ks) {
        const int kb = ks * 16;
        uint32_t ah[2][4], al[2][4], bh[2][4], bl[2][4];
#pragma unroll
        for (int mt = 0; mt < 2; ++mt) {
            uint32_t off = (uint32_t)((mrow + mt * 16 + a_row) * LDN_B + (kb + a_koff) * 2);
            ldsm4(aHi + off, ah[mt]);
            ldsm4(aLo + off, al[mt]);
        }
#pragma unroll
        for (int p = 0; p < 2; ++p) {
            uint32_t off = (uint32_t)(((ncol + p * 16 + b_nrow) * LDA + kb + b_koff) * 2);
            ldsm4(wHi + off, bh[p]);
            ldsm4(wLo + off, bl[p]);
        }
#pragma unroll
        for (int p = 0; p < 2; ++p)
#pragma unroll
            for (int h = 0; h < 2; ++h)
#pragma unroll
                for (int mt = 0; mt < 2; ++mt) {
                    mma16816(d[mt][p * 2 + h], ah[mt], bh[p][2 * h], bh[p][2 * h + 1]);
                    mma16816(d[mt][p * 2 + h], ah[mt], bl[p][2 * h], bl[p][2 * h + 1]);
                    mma16816(d[mt][p * 2 + h], al[mt], bh[p][2 * h], bh[p][2 * h + 1]);
                }
    }
}

__global__ __launch_bounds__(512, 1)
void node_mlp_mma_kernel(const float* __restrict__ tagg,
                         const float* __restrict__ cnt,
                         const int* __restrict__ batch,
                         const __nv_bfloat16* __restrict__ xhi_r,
                         const __nv_bfloat16* __restrict__ xlo_r,
                         const unsigned char* __restrict__ wbase,  // W1a hi/lo, Wc hi/lo, W2 hi/lo
                         const float* __restrict__ b1, const float* __restrict__ b2,
                         const float* __restrict__ bc,
                         const float* __restrict__ uprime,
                         float* __restrict__ xout,                 // may be null (skip fp32 write)
                         float* __restrict__ xsum,
                         __nv_bfloat16* __restrict__ xhi_w,
                         __nv_bfloat16* __restrict__ xlo_w)
{
    extern __shared__ char smc[];
    float* rcp = (float*)(smc + NSM_RCP);
    int*   bat = (int*)(smc + NSM_BAT);
    float* b1s = (float*)(smc + NSM_B1);
    float* b2s = (float*)(smc + NSM_B2);
    float* cfl = (float*)(smc + NSM_CF);
    float* bcs = (float*)(smc + NSM_BC);

    const uint32_t sbase = smem_u32(smc);
    const uint32_t aHi = sbase + NA_HI, aLo = sbase + NA_LO;
    const uint32_t wHi = sbase + NW_HI, wLo = sbase + NW_LO;

    const int tid = threadIdx.x, warp = tid >> 5, lane = tid & 31;
    const int n0 = blockIdx.x * 128;

    if (tid < 128) {
        int n = n0 + tid;
        if (n < N_NODES) {
            float c = cnt[n];
            rcp[tid] = 1.f / fmaxf(c, 1.f);
            cfl[tid] = (c > 0.f) ? 1.f : 0.f;
            bat[tid] = batch[n];
        } else {
            rcp[tid] = 0.f; cfl[tid] = 0.f; bat[tid] = 0;
        }
        b1s[tid] = b1[tid]; b2s[tid] = b2[tid]; bcs[tid] = bc[tid];
    }
    {
        uint4* dw = (uint4*)(smc + NW_HI);
        const uint4* sw = (const uint4*)wbase;
        for (int i = tid; i < (2 * WTILE_BYTES) / 16; i += 512) dw[i] = sw[i];
    }
    __syncthreads();

    // A: x part (cols 0..127) from pre-split buffers
    for (int idx = tid; idx < 128 * 16; idx += 512) {
        int r = idx >> 4, q = idx & 15;
        int n = n0 + r;
        uint4 h = make_uint4(0, 0, 0, 0), l = make_uint4(0, 0, 0, 0);
        if (n < N_NODES) {
            h = *(const uint4*)(xhi_r + (size_t)n * D + q * 8);
            l = *(const uint4*)(xlo_r + (size_t)n * D + q * 8);
        }
        *(uint4*)(smc + NA_HI + r * LDN_B + q * 16) = h;
        *(uint4*)(smc + NA_LO + r * LDN_B + q * 16) = l;
    }
    // A: Tmean part (cols 128..255): scale + split
    for (int idx = tid; idx < 128 * 64; idx += 512) {
        int r = idx >> 6, c2 = idx & 63;
        int n = n0 + r;
        float2 v = make_float2(0.f, 0.f);
        if (n < N_NODES) v = *(const float2*)(tagg + (size_t)n * D + c2 * 2);
        float s = rcp[r];
        v.x *= s; v.y *= s;
        float l0 = v.x - __bfloat162float(__float2bfloat16_rn(v.x));
        float l1 = v.y - __bfloat162float(__float2bfloat16_rn(v.y));
        *(uint32_t*)(smc + NA_HI + r * LDN_B + 256 + c2 * 4) = pack_bf16_hi(v.x, v.y);
        *(uint32_t*)(smc + NA_LO + r * LDN_B + 256 + c2 * 4) = pack_bf16_hi(l0, l1);
    }
    __syncthreads();

    const int mrow = (warp >> 2) * 32;
    const int ncol = (warp & 3) * 32;
    const int crow = lane >> 2, ccol = (lane & 3) * 2;

    float d[2][4][4];
#pragma unroll
    for (int mt = 0; mt < 2; ++mt)
#pragma unroll
        for (int nt = 0; nt < 4; ++nt)
#pragma unroll
            for (int q = 0; q < 4; ++q) d[mt][nt][q] = 0.f;

    // GEMM1a: x @ W1a
    gemm_split32n(aHi, aLo, wHi, wLo, mrow, ncol, lane, d);
    __syncthreads();
    {
        uint4* dw = (uint4*)(smc + NW_HI);
        const uint4* sw = (const uint4*)(wbase + 2 * WTILE_BYTES);
        for (int i = tid; i < (2 * WTILE_BYTES) / 16; i += 512) dw[i] = sw[i];
    }
    __syncthreads();
    // GEMM1b: Tmean @ Wc
    gemm_split32n(aHi + 256, aLo + 256, wHi, wLo, mrow, ncol, lane, d);

    // Epilogue 1: h = relu(d + b1 + U'[bat] + bc*cflag), split, T -> A cols 0..127
#pragma unroll
    for (int mt = 0; mt < 2; ++mt) {
        const int r0 = mrow + mt * 16 + crow, r1 = r0 + 8;
        const int bb0 = bat[r0], bb1 = bat[r1];
        const float cf0 = cfl[r0], cf1 = cfl[r1];
#pragma unroll
        for (int nt = 0; nt < 4; ++nt) {
            const int col = ncol + nt * 8 + ccol;
            float2 u0 = *(const float2*)(uprime + (size_t)bb0 * D + col);
            float2 u1 = *(const float2*)(uprime + (size_t)bb1 * D + col);
            float f0 = fmaxf(d[mt][nt][0] + b1s[col]     + u0.x + bcs[col]     * cf0, 0.f);
            float f1 = fmaxf(d[mt][nt][1] + b1s[col + 1] + u0.y + bcs[col + 1] * cf0, 0.f);
            float f2 = fmaxf(d[mt][nt][2] + b1s[col]     + u1.x + bcs[col]     * cf1, 0.f);
            float f3 = fmaxf(d[mt][nt][3] + b1s[col + 1] + u1.y + bcs[col + 1] * cf1, 0.f);
            uint32_t o0 = (uint32_t)(r0 * LDN_B + col * 2);
            uint32_t o1 = (uint32_t)(r1 * LDN_B + col * 2);
            *(uint32_t*)(smc + NA_HI + o0) = pack_bf16_hi(f0, f1);
            *(uint32_t*)(smc + NA_HI + o1) = pack_bf16_hi(f2, f3);
            float l0 = f0 - __bfloat162float(__float2bfloat16_rn(f0));
            float l1 = f1 - __bfloat162float(__float2bfloat16_rn(f1));
            float l2 = f2 - __bfloat162float(__float2bfloat16_rn(f2));
            float l3 = f3 - __bfloat162float(__float2bfloat16_rn(f3));
            *(uint32_t*)(smc + NA_LO + o0) = pack_bf16_hi(l0, l1);
            *(uint32_t*)(smc + NA_LO + o1) = pack_bf16_hi(l2, l3);
        }
    }
    __syncthreads();
    {
        uint4* dw = (uint4*)(smc + NW_HI);
        const uint4* sw = (const uint4*)(wbase + 4 * WTILE_BYTES);
        for (int i = tid; i < (2 * WTILE_BYTES) / 16; i += 512) dw[i] = sw[i];
    }
    __syncthreads();

#pragma unroll
    for (int mt = 0; mt < 2; ++mt)
#pragma unroll
        for (int nt = 0; nt < 4; ++nt)
#pragma unroll
            for (int q = 0; q < 4; ++q) d[mt][nt][q] = 0.f;

    // GEMM2: T @ W2
    gemm_split32n(aHi, aLo, wHi, wLo, mrow, ncol, lane, d);

    // Epilogue 2
#pragma unroll
    for (int mt = 0; mt < 2; ++mt) {
        const int r0 = mrow + mt * 16 + crow, r1 = r0 + 8;
        const int nn0 = n0 + r0, nn1 = n0 + r1;
        const int bb0 = bat[r0], bb1 = bat[r1];
#pragma unroll
        for (int nt = 0; nt < 4; ++nt) {
            const int col = ncol + nt * 8 + ccol;
            float o0 = d[mt][nt][0] + b2s[col];
            float o1 = d[mt][nt][1] + b2s[col + 1];
            float o2 = d[mt][nt][2] + b2s[col];
            float o3 = d[mt][nt][3] + b2s[col + 1];
            if (nn0 < N_NODES) {
                if (xout) *(float2*)(xout + (size_t)nn0 * D + col) = make_float2(o0, o1);
                *(uint32_t*)(xhi_w + (size_t)nn0 * D + col) = pack_bf16_hi(o0, o1);
                float l0 = o0 - __bfloat162float(__float2bfloat16_rn(o0));
                float l1 = o1 - __bfloat162float(__float2bfloat16_rn(o1));
                *(uint32_t*)(xlo_w + (size_t)nn0 * D + col) = pack_bf16_hi(l0, l1);
                red_add_v2(xsum + (size_t)bb0 * D + col, o0, o1);
            }
            if (nn1 < N_NODES) {
                if (xout) *(float2*)(xout + (size_t)nn1 * D + col) = make_float2(o2, o3);
                *(uint32_t*)(xhi_w + (size_t)nn1 * D + col) = pack_bf16_hi(o2, o3);
                float l2 = o2 - __bfloat162float(__float2bfloat16_rn(o2));
                float l3 = o3 - __bfloat162float(__float2bfloat16_rn(o3));
                *(uint32_t*)(xlo_w + (size_t)nn1 * D + col) = pack_bf16_hi(l2, l3);
                red_add_v2(xsum + (size_t)bb1 * D + col, o2, o3);
            }
        }
    }
}

// ===========================================================================
// Global MLP (unchanged)
// ===========================================================================
__global__ __launch_bounds__(256, 1)
void global_mlp_kernel(const float* __restrict__ u,
                       const float* __restrict__ xsum,
                       const float* __restrict__ bcnt,
                       const float* __restrict__ w1, const float* __restrict__ b1,
                       const float* __restrict__ w2, const float* __restrict__ b2,
                       float* __restrict__ uout)
{
    extern __shared__ float sm[];
    float* G  = sm;              // [64][256]
    float* Hh = G + 64 * 256;    // [64][EPAD]

    const int tid = threadIdx.x;
    const int tx  = tid & 15;
    const int ty  = tid >> 4;

    for (int idx = tid; idx < 64 * 128; idx += 256) {
        int b = idx >> 7, c = idx & 127;
        G[b * 256 + c]       = u[idx];
        G[b * 256 + 128 + c] = xsum[idx] / fmaxf(bcnt[b], 1.0f);
    }
    __syncthreads();

    float acc[4][8];
#pragma unroll
    for (int i = 0; i < 4; ++i)
#pragma unroll
        for (int j = 0; j < 8; ++j) acc[i][j] = 0.f;

#pragma unroll 4
    for (int k = 0; k < 256; ++k) {
        float ra[4];
#pragma unroll
        for (int i = 0; i < 4; ++i) ra[i] = G[(ty * 4 + i) * 256 + k];
        float4 rb0 = __ldg((const float4*)&w1[k * 128 + tx * 8]);
        float4 rb1 = __ldg((const float4*)&w1[k * 128 + tx * 8 + 4]);
        float rb[8] = {rb0.x, rb0.y, rb0.z, rb0.w, rb1.x, rb1.y, rb1.z, rb1.w};
#pragma unroll
        for (int i = 0; i < 4; ++i)
#pragma unroll
            for (int j = 0; j < 8; ++j) acc[i][j] = fmaf(ra[i], rb[j], acc[i][j]);
    }

    {
        float bv[8];
#pragma unroll
        for (int j = 0; j < 8; ++j) bv[j] = b1[tx * 8 + j];
#pragma unroll
        for (int i = 0; i < 4; ++i) {
#pragma unroll
            for (int j = 0; j < 8; ++j) acc[i][j] = fmaxf(acc[i][j] + bv[j], 0.f);
            *(float4*)&Hh[(ty * 4 + i) * EPAD + tx * 8]     = make_float4(acc[i][0], acc[i][1], acc[i][2], acc[i][3]);
            *(float4*)&Hh[(ty * 4 + i) * EPAD + tx * 8 + 4] = make_float4(acc[i][4], acc[i][5], acc[i][6], acc[i][7]);
        }
    }
    __syncthreads();

#pragma unroll
    for (int i = 0; i < 4; ++i)
#pragma unroll
        for (int j = 0; j < 8; ++j) acc[i][j] = 0.f;

#pragma unroll 4
    for (int k = 0; k < 128; ++k) {
        float ra[4];
#pragma unroll
        for (int i = 0; i < 4; ++i) ra[i] = Hh[(ty * 4 + i) * EPAD + k];
        float4 rb0 = __ldg((const float4*)&w2[k * 128 + tx * 8]);
        float4 rb1 = __ldg((const float4*)&w2[k * 128 + tx * 8 + 4]);
        float rb[8] = {rb0.x, rb0.y, rb0.z, rb0.w, rb1.x, rb1.y, rb1.z, rb1.w};
#pragma unroll
        for (int i = 0; i < 4; ++i)
#pragma unroll
            for (int j = 0; j < 8; ++j) acc[i][j] = fmaf(ra[i], rb[j], acc[i][j]);
    }

    {
        float bv[8];
#pragma unroll
        for (int j = 0; j < 8; ++j) bv[j] = b2[tx * 8 + j];
#pragma unroll
        for (int i = 0; i < 4; ++i) {
            int b = ty * 4 + i;
            *(float4*)&uout[b * D + tx * 8]     = make_float4(acc[i][0] + bv[0], acc[i][1] + bv[1],
                                                              acc[i][2] + bv[2], acc[i][3] + bv[3]);
            *(float4*)&uout[b * D + tx * 8 + 4] = make_float4(acc[i][4] + bv[4], acc[i][5] + bv[5],
                                                              acc[i][6] + bv[6], acc[i][7] + bv[7]);
        }
    }
}

// ===========================================================================
// Host side
// ===========================================================================
static const int GLOB_SMEM = (64 * 256 + 64 * EPAD) * 4;

extern "C" void kernel_launch(void* const* d_in, const int* in_sizes, int n_in,
                              void* d_out, int out_size) {
    const float* x0    = (const float*)d_in[0];
    const int*   ei    = (const int*)d_in[1];      // int32 (JAX x64 disabled)
    const float* u0    = (const float*)d_in[2];
    const int*   batch = (const int*)d_in[3];      // int32
    const float* n1w1 = (const float*)d_in[4];
    const float* n1b1 = (const float*)d_in[5];
    const float* n1w2 = (const float*)d_in[6];
    const float* n1b2 = (const float*)d_in[7];
    const float* n2w1 = (const float*)d_in[8];
    const float* n2b1 = (const float*)d_in[9];
    const float* n2w2 = (const float*)d_in[10];
    const float* n2b2 = (const float*)d_in[11];
    const float* gw1  = (const float*)d_in[12];
    const float* gb1  = (const float*)d_in[13];
    const float* gw2  = (const float*)d_in[14];
    const float* gb2  = (const float*)d_in[15];
    float* out = (float*)d_out;

    float *pu, *pagg, *pcnt, *pxsum, *pbcnt, *pup, *pbc;
    unsigned char* pwt;
    __nv_bfloat16 *pxhi, *pxlo;
    cudaGetSymbolAddress((void**)&pu,    g_u);
    cudaGetSymbolAddress((void**)&pagg,  g_agg);
    cudaGetSymbolAddress((void**)&pcnt,  g_cnt);
    cudaGetSymbolAddress((void**)&pxsum, g_xsum);
    cudaGetSymbolAddress((void**)&pbcnt, g_bcnt);
    cudaGetSymbolAddress((void**)&pup,   g_uprime);
    cudaGetSymbolAddress((void**)&pbc,   g_bc);
    cudaGetSymbolAddress((void**)&pwt,   g_wt);
    cudaGetSymbolAddress((void**)&pxhi,  g_xhi);
    cudaGetSymbolAddress((void**)&pxlo,  g_xlo);
    float* ubuf[2] = {pu, pu + (size_t)NB * D};
    __nv_bfloat16* xhib[2] = {pxhi, pxhi + (size_t)N_NODES * D};
    __nv_bfloat16* xlob[2] = {pxlo, pxlo + (size_t)N_NODES * D};

    cudaFuncSetAttribute(edge_mlp_mma_kernel, cudaFuncAttributeMaxDynamicSharedMemorySize, EDGE_SMEM);
    cudaFuncSetAttribute(node_mlp_mma_kernel, cudaFuncAttributeMaxDynamicSharedMemorySize, NODE2_SMEM);
    cudaFuncSetAttribute(global_mlp_kernel,   cudaFuncAttributeMaxDynamicSharedMemorySize, GLOB_SMEM);

    // one-time: counts, Wc/bc, weight tiles, layer-0 x split
    cudaMemsetAsync(pcnt,  0, N_NODES * sizeof(float));
    cudaMemsetAsync(pbcnt, 0, NB * sizeof(float));
    count_edges_kernel<<<(N_EDGES + 255) / 256, 256>>>(ei, pcnt);
    count_batch_kernel<<<(N_NODES + 255) / 256, 256>>>(batch, pbcnt);
    wc_kernel<<<NLAYERS * 128, 128>>>(n1w2, n2w1, n1b2);
    prep_weights_kernel<<<20, 256>>>(n1w1, n1w2, n2w1, n2w2);
    split_x_kernel<<<(N_NODES * (D / 2) + 255) / 256, 256>>>(x0);

    const float* uc = u0;
    for (int l = 0; l < NLAYERS; ++l) {
        const int rd = l & 1, wr = rd ^ 1;
        cudaMemsetAsync(pagg,  0, (size_t)N_NODES * D * sizeof(float));
        cudaMemsetAsync(pxsum, 0, (size_t)NB * D * sizeof(float));

        const unsigned char* ew1hi = pwt + (size_t)(l * 4 + 0) * WTILE_BYTES;
        const unsigned char* ew1lo = pwt + (size_t)(l * 4 + 1) * WTILE_BYTES;
        const unsigned char* nwb   = pwt + (size_t)(16 + l * 6) * WTILE_BYTES;

        edge_mlp_mma_kernel<<<EDGE_GRID, ETHREADS, EDGE_SMEM>>>(
            ei, xhib[rd], xlob[rd], ew1hi, ew1lo,
            n1b1 + (size_t)l * D, pagg);

        uprime_kernel<<<NB, 128>>>(uc, n2w1 + (size_t)l * 384 * D + 256 * D);

        float* xn = (l == NLAYERS - 1) ? out : nullptr;
        node_mlp_mma_kernel<<<NT_NODE, 512, NODE2_SMEM>>>(
            pagg, pcnt, batch, xhib[rd], xlob[rd], nwb,
            n2b1 + (size_t)l * D, n2b2 + (size_t)l * D, pbc + (size_t)l * D, pup,
            xn, pxsum, xhib[wr], xlob[wr]);

        float* un = (l == NLAYERS - 1) ? out + (size_t)N_NODES * D : ubuf[l & 1];
        global_mlp_kernel<<<1, 256, GLOB_SMEM>>>(
            uc, pxsum, pbcnt,
            gw1 + (size_t)l * 256 * D, gb1 + (size_t)l * D,
            gw2 + (size_t)l * D * D,   gb2 + (size_t)l * D,
            un);

        uc = un;
    }
}